// round 9
// baseline (speedup 1.0000x reference)
#include <cuda_runtime.h>
#include <math.h>
#include <stdint.h>

#define NB 2
#define NS 1024
#define NT (NB*NS)      // 2048 tokens
#define ND 2048
#define NF 8192
#define NE 4

// ---------------- persistent scratch (device globals) ----------------------
__device__ float g_gatew[NE*NT];
__device__ int   g_counts[NE];
__device__ int   g_lists[NE*NT];
__device__ float g_H [(size_t)NE*NT*NF];   // H = silu(G)*U, tf32-rounded; rows >= Me stay 0
__device__ float g_Xr[(size_t)NT*ND];      // x, tf32-rounded

// ---------------- helpers ---------------------------------------------------
__device__ __forceinline__ uint32_t smem_u32(const void* p) {
    uint32_t a;
    asm("{ .reg .u64 t; cvta.to.shared.u64 t, %1; cvt.u32.u64 %0, t; }" : "=r"(a) : "l"(p));
    return a;
}
__device__ __forceinline__ unsigned f2tf(float f) {
    unsigned u; asm("cvt.rna.tf32.f32 %0, %1;" : "=r"(u) : "f"(f)); return u;
}
__device__ __forceinline__ float tf32r(float f) { return __uint_as_float(f2tf(f)); }

__device__ __forceinline__ void cpa16(uint32_t dst, const float* src) {
    asm volatile("cp.async.cg.shared.global [%0], [%1], 16;" :: "r"(dst), "l"(src));
}
__device__ __forceinline__ void cpa_commit() { asm volatile("cp.async.commit_group;"); }
__device__ __forceinline__ void cpa_wait1()  { asm volatile("cp.async.wait_group 1;"); }

__device__ __forceinline__ void mma8(float c[4], const unsigned a[4], const unsigned b[2]) {
    asm volatile(
        "mma.sync.aligned.m16n8k8.row.col.f32.tf32.tf32.f32 "
        "{%0,%1,%2,%3}, {%4,%5,%6,%7}, {%8,%9}, {%0,%1,%2,%3};"
        : "+f"(c[0]), "+f"(c[1]), "+f"(c[2]), "+f"(c[3])
        : "r"(a[0]), "r"(a[1]), "r"(a[2]), "r"(a[3]), "r"(b[0]), "r"(b[1]));
}
// ldmatrix x4 on stride-36 A tile (lane mapping validated; 36 ≡ 4 mod 32 -> conflict-free)
__device__ __forceinline__ void ldmA(unsigned r[4], uint32_t addr) {
    asm volatile("ldmatrix.sync.aligned.m8n8.x4.shared.b16 {%0,%1,%2,%3}, [%4];"
        : "=r"(r[0]), "=r"(r[1]), "=r"(r[2]), "=r"(r[3]) : "r"(addr));
}

// ---------------- trivial kernels -------------------------------------------
__global__ void zero_kernel(float* __restrict__ out) {
    size_t n = (size_t)NT * ND;
    for (size_t i = blockIdx.x * (size_t)blockDim.x + threadIdx.x; i < n;
         i += (size_t)gridDim.x * blockDim.x) out[i] = 0.f;
    if (blockIdx.x == 0 && threadIdx.x < NE) g_counts[threadIdx.x] = 0;
}

__global__ void round_copy(const float* __restrict__ src, float* __restrict__ dst, size_t n4) {
    for (size_t i = blockIdx.x * (size_t)blockDim.x + threadIdx.x; i < n4;
         i += (size_t)gridDim.x * blockDim.x) {
        float4 v = ((const float4*)src)[i];
        ((float4*)dst)[i] = make_float4(tf32r(v.x), tf32r(v.y), tf32r(v.z), tf32r(v.w));
    }
}

__global__ void router_kernel(const float* __restrict__ x, const float* __restrict__ Wr) {
    int t = blockIdx.x;
    const float* xr = x + (size_t)t * ND;
    float acc[NE] = {0.f, 0.f, 0.f, 0.f};
    for (int d = threadIdx.x; d < ND; d += blockDim.x) {
        float xv = xr[d];
        float4 w = *(const float4*)(Wr + d * NE);
        acc[0] += xv * w.x; acc[1] += xv * w.y; acc[2] += xv * w.z; acc[3] += xv * w.w;
    }
    __shared__ float sred[NE][8];
    int lane = threadIdx.x & 31, wid = threadIdx.x >> 5;
    #pragma unroll
    for (int e = 0; e < NE; e++) {
        float s = acc[e];
        #pragma unroll
        for (int off = 16; off > 0; off >>= 1) s += __shfl_down_sync(0xffffffffu, s, off);
        if (lane == 0) sred[e][wid] = s;
    }
    __syncthreads();
    if (threadIdx.x == 0) {
        float l[NE];
        #pragma unroll
        for (int e = 0; e < NE; e++) {
            float s = 0.f;
            #pragma unroll
            for (int w = 0; w < 8; w++) s += sred[e][w];
            l[e] = s;
        }
        float mx = fmaxf(fmaxf(l[0], l[1]), fmaxf(l[2], l[3]));
        float ex[NE], ssum = 0.f;
        #pragma unroll
        for (int e = 0; e < NE; e++) { ex[e] = expf(l[e] - mx); ssum += ex[e]; }
        float p[NE];
        #pragma unroll
        for (int e = 0; e < NE; e++) p[e] = ex[e] / ssum;
        int i1 = 0;
        #pragma unroll
        for (int e = 1; e < NE; e++) if (p[e] > p[i1]) i1 = e;
        int i2 = -1;
        #pragma unroll
        for (int e = 0; e < NE; e++)
            if (e != i1 && (i2 < 0 || p[e] > p[i2])) i2 = e;
        #pragma unroll
        for (int e = 0; e < NE; e++)
            g_gatew[e * NT + t] = (e == i1 || e == i2) ? p[e] : 0.f;
    }
}

__global__ void compact_kernel() {
    for (int t = threadIdx.x; t < NT; t += blockDim.x) {
        #pragma unroll
        for (int e = 0; e < NE; e++) {
            if (g_gatew[e * NT + t] > 0.f) {
                int p = atomicAdd(&g_counts[e], 1);
                g_lists[e * NT + p] = t;
            }
        }
    }
}

// ---------------------------------------------------------------------------
// GATE+UP fused GEMM (tf32 mma.sync, cp.async 3-stage pipeline, BK=32,
// 256 thr, 2 CTA/SM). Block tile M=128, N=64/matrix. 8 warps 4x2 -> 32x32 each.
// A: [128 rows][32 k] row stride 36 words (ldmatrix, conflict-free)
// Bg/Bu: [32 k][64 n] row stride 72 words (conflict-free)
// ---------------------------------------------------------------------------
#define GU_AF 4608          // 128*36 floats
#define GU_BF 2304          // 32*72 floats
#define GU_STAGEF (GU_AF + 2*GU_BF)           // 9216 floats = 36864 B
#define GU_SMEM (3 * GU_STAGEF * 4)           // 110592 B

__global__ __launch_bounds__(256, 2) void gateup_tc(const float* __restrict__ X,
                                                    const float* __restrict__ Wg,
                                                    const float* __restrict__ Wu) {
    const int e  = blockIdx.z;
    const int Me = g_counts[e];
    const int m0 = blockIdx.x * 128;
    if (m0 >= Me) return;
    const int n0 = blockIdx.y * 64;

    extern __shared__ float smem[];
    const uint32_t sb0 = smem_u32(smem);

    const int tid  = threadIdx.x;
    const int warp = tid >> 5;
    const int lane = tid & 31;
    const int g4   = lane >> 2;
    const int t4   = lane & 3;
    const int wm   = warp >> 1;        // 0..3
    const int wn   = warp & 1;         // 0..1

    // A staging: row = tid>>1 (0..127), k-half = (tid&1)*16; 4x16B
    const int ar = tid >> 1;
    const int ah = (tid & 1) * 16;
    int mrow = m0 + ar; if (mrow >= Me) mrow = Me - 1;
    const float* asrc = X + (size_t)g_lists[e * NT + mrow] * ND + ah;
    const uint32_t adst = sb0 + (ar * 36 + ah) * 4;
    // B staging: per matrix 512 fl4 chunks; 2 per thread per matrix
    //   chunk c = j*256 + tid: row = c>>4 (0..31), c4 = c&15
    const float* bgbase = Wg + (size_t)e * ND * NF + n0;
    const float* bubase = Wu + (size_t)e * ND * NF + n0;

    float accG[2][4][4], accU[2][4][4];
    #pragma unroll
    for (int i = 0; i < 2; i++)
        #pragma unroll
        for (int j = 0; j < 4; j++)
            #pragma unroll
            for (int k = 0; k < 4; k++) { accG[i][j][k] = 0.f; accU[i][j][k] = 0.f; }

    const int KT = ND / 32;    // 64
    auto issue = [&](int it) {
        const uint32_t so = (uint32_t)(it % 3) * (GU_STAGEF * 4);
        const size_t ka = (size_t)it * 32;
        #pragma unroll
        for (int q = 0; q < 4; q++)
            cpa16(adst + so + q * 16, asrc + ka + q * 4);
        #pragma unroll
        for (int j = 0; j < 2; j++) {
            const int c = j * 256 + tid;
            const int row = c >> 4, c4 = c & 15;
            cpa16(sb0 + so + (GU_AF + row * 72 + c4 * 4) * 4,
                  bgbase + (ka + row) * NF + c4 * 4);
            cpa16(sb0 + so + (GU_AF + GU_BF + row * 72 + c4 * 4) * 4,
                  bubase + (ka + row) * NF + c4 * 4);
        }
    };

    issue(0); cpa_commit();
    issue(1); cpa_commit();

    // ldmatrix lane offset (bytes): row (wm*32 + (lane&15)), k-offset (lane>=16)*4
    const uint32_t aldm = ((wm * 32 + (lane & 15)) * 36 + ((lane >> 4) << 2)) * 4;

    for (int it = 0; it < KT; ++it) {
        cpa_wait1();               // groups {it, it+1} pending -> group it complete
        __syncthreads();
        if (it + 2 < KT) issue(it + 2);
        cpa_commit();

        const uint32_t sA = sb0 + (uint32_t)(it % 3) * (GU_STAGEF * 4);
        const float* Bg = smem + (it % 3) * GU_STAGEF + GU_AF;
        const float* Bu = Bg + GU_BF;

        #pragma unroll
        for (int ks = 0; ks < 32; ks += 8) {
            unsigned a[2][4];
            #pragma unroll
            for (int mi = 0; mi < 2; mi++)
                ldmA(a[mi], sA + aldm + (mi * 16 * 36 + ks) * 4);
            #pragma unroll
            for (int ni = 0; ni < 4; ni++) {
                const int nb = wn * 32 + ni * 8 + g4;
                unsigned bg[2] = { f2tf(Bg[(ks + t4) * 72 + nb]),
                                   f2tf(Bg[(ks + t4 + 4) * 72 + nb]) };
                unsigned bu[2] = { f2tf(Bu[(ks + t4) * 72 + nb]),
                                   f2tf(Bu[(ks + t4 + 4) * 72 + nb]) };
                #pragma unroll
                for (int mi = 0; mi < 2; mi++) {
                    mma8(accG[mi][ni], a[mi], bg);
                    mma8(accU[mi][ni], a[mi], bu);
                }
            }
        }
    }

    // epilogue: H = tf32( silu(G)*U )
    #pragma unroll
    for (int mi = 0; mi < 2; mi++) {
        #pragma unroll
        for (int half = 0; half < 2; half++) {
            const int m = m0 + wm * 32 + mi * 16 + g4 + half * 8;
            if (m >= Me) continue;
            float* Hrow = g_H + ((size_t)e * NT + m) * NF + n0 + wn * 32;
            #pragma unroll
            for (int ni = 0; ni < 4; ni++) {
                float gv0 = accG[mi][ni][half * 2],     uv0 = accU[mi][ni][half * 2];
                float gv1 = accG[mi][ni][half * 2 + 1], uv1 = accU[mi][ni][half * 2 + 1];
                float h0 = tf32r(gv0 / (1.f + expf(-gv0)) * uv0);
                float h1 = tf32r(gv1 / (1.f + expf(-gv1)) * uv1);
                *(float2*)(Hrow + ni * 8 + 2 * t4) = make_float2(h0, h1);
            }
        }
    }
}

// ---------------------------------------------------------------------------
// DOWN GEMM + combine (tf32 mma.sync, cp.async 3-stage pipeline, BK=32,
// 256 thr, 2 CTA/SM). Block tile 128x128. 8 warps 4x2 -> 32x64 warptile.
// A: [128][32] stride 36 (ldmatrix); B: [32][128] stride 136.
// ---------------------------------------------------------------------------
#define DN_AF 4608          // 128*36
#define DN_BF 4352          // 32*136
#define DN_STAGEF (DN_AF + DN_BF)             // 8960 floats = 35840 B
#define DN_SMEM (3 * DN_STAGEF * 4)           // 107520 B

__global__ __launch_bounds__(256, 2) void down_tc(const float* __restrict__ Wd,
                                                  float* __restrict__ OUT) {
    const int e  = blockIdx.z;
    const int Me = g_counts[e];
    const int m0 = blockIdx.x * 128;
    if (m0 >= Me) return;
    const int n0 = blockIdx.y * 128;

    extern __shared__ float smem[];
    const uint32_t sb0 = smem_u32(smem);

    const int tid  = threadIdx.x;
    const int warp = tid >> 5;
    const int lane = tid & 31;
    const int g4   = lane >> 2;
    const int t4   = lane & 3;
    const int wm   = warp >> 1;
    const int wn   = warp & 1;

    const int ar = tid >> 1;
    const int ah = (tid & 1) * 16;
    const float* asrc = g_H + ((size_t)e * NT + m0 + ar) * NF + ah;  // rows>=Me read zeros
    const uint32_t adst = sb0 + (ar * 36 + ah) * 4;

    // B staging: 1024 fl4 chunks; 4 per thread: c = j*256+tid: row = c>>5, c4 = c&31
    const float* bbase = Wd + (size_t)e * NF * ND + n0;

    float acc[2][8][4];
    #pragma unroll
    for (int i = 0; i < 2; i++)
        #pragma unroll
        for (int j = 0; j < 8; j++)
            #pragma unroll
            for (int k = 0; k < 4; k++) acc[i][j][k] = 0.f;

    const int KT = NF / 32;   // 256
    auto issue = [&](int it) {
        const uint32_t so = (uint32_t)(it % 3) * (DN_STAGEF * 4);
        const size_t ka = (size_t)it * 32;
        #pragma unroll
        for (int q = 0; q < 4; q++)
            cpa16(adst + so + q * 16, asrc + ka + q * 4);
        #pragma unroll
        for (int j = 0; j < 4; j++) {
            const int c = j * 256 + tid;
            const int row = c >> 5, c4 = c & 31;
            cpa16(sb0 + so + (DN_AF + row * 136 + c4 * 4) * 4,
                  bbase + (ka + row) * ND + c4 * 4);
        }
    };

    issue(0); cpa_commit();
    issue(1); cpa_commit();

    const uint32_t aldm = ((wm * 32 + (lane & 15)) * 36 + ((lane >> 4) << 2)) * 4;

    for (int it = 0; it < KT; ++it) {
        cpa_wait1();
        __syncthreads();
        if (it + 2 < KT) issue(it + 2);
        cpa_commit();

        const uint32_t sA = sb0 + (uint32_t)(it % 3) * (DN_STAGEF * 4);
        const float* Bs = smem + (it % 3) * DN_STAGEF + DN_AF;

        #pragma unroll
        for (int ks = 0; ks < 32; ks += 8) {
            unsigned a[2][4];
            #pragma unroll
            for (int mi = 0; mi < 2; mi++)
                ldmA(a[mi], sA + aldm + (mi * 16 * 36 + ks) * 4);
            #pragma unroll
            for (int ni = 0; ni < 8; ni++) {
                const int nb = wn * 64 + ni * 8 + g4;
                unsigned b[2] = { f2tf(Bs[(ks + t4) * 136 + nb]),
                                  f2tf(Bs[(ks + t4 + 4) * 136 + nb]) };
                #pragma unroll
                for (int mi = 0; mi < 2; mi++)
                    mma8(acc[mi][ni], a[mi], b);
            }
        }
    }

    #pragma unroll
    for (int mi = 0; mi < 2; mi++) {
        #pragma unroll
        for (int half = 0; half < 2; half++) {
            const int m = m0 + wm * 32 + mi * 16 + g4 + half * 8;
            if (m >= Me) continue;
            const int tok = g_lists[e * NT + m];
            const float w = g_gatew[e * NT + tok];
            float* dst = OUT + (size_t)tok * ND + n0 + wn * 64;
            #pragma unroll
            for (int ni = 0; ni < 8; ni++) {
                atomicAdd(dst + ni * 8 + 2 * t4,     w * acc[mi][ni][half * 2]);
                atomicAdd(dst + ni * 8 + 2 * t4 + 1, w * acc[mi][ni][half * 2 + 1]);
            }
        }
    }
}

// ---------------------------------------------------------------------------
extern "C" void kernel_launch(void* const* d_in, const int* in_sizes, int n_in,
                              void* d_out, int out_size) {
    const float* x  = (const float*)d_in[0];
    const float* Wr = (const float*)d_in[1];
    const float* Wg = (const float*)d_in[2];
    const float* Wu = (const float*)d_in[3];
    const float* Wd = (const float*)d_in[4];
    float* out = (float*)d_out;

    cudaFuncSetAttribute(gateup_tc, cudaFuncAttributeMaxDynamicSharedMemorySize, GU_SMEM);
    cudaFuncSetAttribute(down_tc,   cudaFuncAttributeMaxDynamicSharedMemorySize, DN_SMEM);

    float* xr;  cudaGetSymbolAddress((void**)&xr, g_Xr);

    zero_kernel<<<2048, 256>>>(out);
    router_kernel<<<NT, 256>>>(x, Wr);
    compact_kernel<<<1, 256>>>();
    round_copy<<<2048, 256>>>(x, xr, (size_t)NT * ND / 4);

    gateup_tc<<<dim3(NT/128, NF/64, NE), 256, GU_SMEM>>>(xr, Wg, Wu);
    down_tc  <<<dim3(NT/128, ND/128, NE), 256, DN_SMEM>>>(Wd, out);
}

// round 10
// speedup vs baseline: 1.0581x; 1.0581x over previous
#include <cuda_runtime.h>
#include <math.h>
#include <stdint.h>

#define NB 2
#define NS 1024
#define NT (NB*NS)      // 2048 tokens
#define ND 2048
#define NF 8192
#define NE 4

// ---------------- persistent scratch (device globals) ----------------------
__device__ float g_gatew[NE*NT];
__device__ int   g_counts[NE];
__device__ int   g_lists[NE*NT];
__device__ float g_H [(size_t)NE*NT*NF];   // H = silu(G)*U, tf32-rounded; rows >= Me stay 0
__device__ float g_Xr[(size_t)NT*ND];      // x, tf32-rounded

// ---------------- helpers ---------------------------------------------------
__device__ __forceinline__ uint32_t smem_u32(const void* p) {
    uint32_t a;
    asm("{ .reg .u64 t; cvta.to.shared.u64 t, %1; cvt.u32.u64 %0, t; }" : "=r"(a) : "l"(p));
    return a;
}
__device__ __forceinline__ unsigned f2tf(float f) {
    unsigned u; asm("cvt.rna.tf32.f32 %0, %1;" : "=r"(u) : "f"(f)); return u;
}
__device__ __forceinline__ float tf32r(float f) { return __uint_as_float(f2tf(f)); }

__device__ __forceinline__ void cpa16(uint32_t dst, const float* src) {
    asm volatile("cp.async.cg.shared.global [%0], [%1], 16;" :: "r"(dst), "l"(src));
}
__device__ __forceinline__ void cpa_commit() { asm volatile("cp.async.commit_group;"); }
__device__ __forceinline__ void cpa_wait3()  { asm volatile("cp.async.wait_group 3;"); }

__device__ __forceinline__ void mma8(float c[4], const unsigned a[4], const unsigned b[2]) {
    asm volatile(
        "mma.sync.aligned.m16n8k8.row.col.f32.tf32.tf32.f32 "
        "{%0,%1,%2,%3}, {%4,%5,%6,%7}, {%8,%9}, {%0,%1,%2,%3};"
        : "+f"(c[0]), "+f"(c[1]), "+f"(c[2]), "+f"(c[3])
        : "r"(a[0]), "r"(a[1]), "r"(a[2]), "r"(a[3]), "r"(b[0]), "r"(b[1]));
}
// ldmatrix x4 on the stride-20 A tile (lane mapping validated: bit-identical results)
__device__ __forceinline__ void ldmA(unsigned r[4], uint32_t addr) {
    asm volatile("ldmatrix.sync.aligned.m8n8.x4.shared.b16 {%0,%1,%2,%3}, [%4];"
        : "=r"(r[0]), "=r"(r[1]), "=r"(r[2]), "=r"(r[3]) : "r"(addr));
}

// ---------------- prep: zero output + counts, round x -> tf32 ---------------
__global__ void prep_kernel(const float* __restrict__ x, float* __restrict__ xr,
                            float* __restrict__ out) {
    const size_t n4 = (size_t)NT * ND / 4;
    const float4 z = make_float4(0.f, 0.f, 0.f, 0.f);
    for (size_t i = blockIdx.x * (size_t)blockDim.x + threadIdx.x; i < n4;
         i += (size_t)gridDim.x * blockDim.x) {
        ((float4*)out)[i] = z;
        float4 v = ((const float4*)x)[i];
        ((float4*)xr)[i] = make_float4(tf32r(v.x), tf32r(v.y), tf32r(v.z), tf32r(v.w));
    }
    if (blockIdx.x == 0 && threadIdx.x < NE) g_counts[threadIdx.x] = 0;
}

__global__ void router_kernel(const float* __restrict__ x, const float* __restrict__ Wr) {
    int t = blockIdx.x;
    const float* xr = x + (size_t)t * ND;
    float acc[NE] = {0.f, 0.f, 0.f, 0.f};
    for (int d = threadIdx.x; d < ND; d += blockDim.x) {
        float xv = xr[d];
        float4 w = *(const float4*)(Wr + d * NE);
        acc[0] += xv * w.x; acc[1] += xv * w.y; acc[2] += xv * w.z; acc[3] += xv * w.w;
    }
    __shared__ float sred[NE][8];
    int lane = threadIdx.x & 31, wid = threadIdx.x >> 5;
    #pragma unroll
    for (int e = 0; e < NE; e++) {
        float s = acc[e];
        #pragma unroll
        for (int off = 16; off > 0; off >>= 1) s += __shfl_down_sync(0xffffffffu, s, off);
        if (lane == 0) sred[e][wid] = s;
    }
    __syncthreads();
    if (threadIdx.x == 0) {
        float l[NE];
        #pragma unroll
        for (int e = 0; e < NE; e++) {
            float s = 0.f;
            #pragma unroll
            for (int w = 0; w < 8; w++) s += sred[e][w];
            l[e] = s;
        }
        float mx = fmaxf(fmaxf(l[0], l[1]), fmaxf(l[2], l[3]));
        float ex[NE], ssum = 0.f;
        #pragma unroll
        for (int e = 0; e < NE; e++) { ex[e] = expf(l[e] - mx); ssum += ex[e]; }
        float p[NE];
        #pragma unroll
        for (int e = 0; e < NE; e++) p[e] = ex[e] / ssum;
        int i1 = 0;
        #pragma unroll
        for (int e = 1; e < NE; e++) if (p[e] > p[i1]) i1 = e;
        int i2 = -1;
        #pragma unroll
        for (int e = 0; e < NE; e++)
            if (e != i1 && (i2 < 0 || p[e] > p[i2])) i2 = e;
        #pragma unroll
        for (int e = 0; e < NE; e++)
            g_gatew[e * NT + t] = (e == i1 || e == i2) ? p[e] : 0.f;
    }
}

__global__ void compact_kernel() {
    for (int t = threadIdx.x; t < NT; t += blockDim.x) {
        #pragma unroll
        for (int e = 0; e < NE; e++) {
            if (g_gatew[e * NT + t] > 0.f) {
                int p = atomicAdd(&g_counts[e], 1);
                g_lists[e * NT + p] = t;
            }
        }
    }
}

// ---------------------------------------------------------------------------
// GATE+UP fused GEMM (tf32 mma.sync, cp.async 5-stage pipeline, 256 thr, 2 CTA/SM)
// Block tile M=128, N=64 (per matrix), K=16.  8 warps 4x2 -> 32x32 warptile each.
// A tile:  [128 rows][16 k] k-contiguous, row stride 20 words (ldmatrix, conflict-free)
// B tiles: [16 k][64 n]  n-contiguous, row stride 72 words (conflict-free)
// A pre-rounded tf32 (g_Xr); B RAW fp32, rounded RNA at fragment load.
// ---------------------------------------------------------------------------
#define GU_AF 2560          // 128*20 floats
#define GU_BF 1152          // 16*72 floats
#define GU_STAGEF (GU_AF + 2*GU_BF)           // 4864 floats = 19456 B
#define GU_SMEM (5 * GU_STAGEF * 4)           // 97280 B

__global__ __launch_bounds__(256, 2) void gateup_tc(const float* __restrict__ X,
                                                    const float* __restrict__ Wg,
                                                    const float* __restrict__ Wu) {
    const int e  = blockIdx.z;
    const int Me = g_counts[e];
    const int m0 = blockIdx.x * 128;
    if (m0 >= Me) return;
    const int n0 = blockIdx.y * 64;

    extern __shared__ float smem[];
    const uint32_t sb0 = smem_u32(smem);

    const int tid  = threadIdx.x;
    const int warp = tid >> 5;
    const int lane = tid & 31;
    const int g4   = lane >> 2;
    const int t4   = lane & 3;
    const int wm   = warp >> 1;        // 0..3
    const int wn   = warp & 1;         // 0..1

    const int ar = tid >> 1;
    const int ah = (tid & 1) * 8;
    int mrow = m0 + ar; if (mrow >= Me) mrow = Me - 1;
    const float* asrc = X + (size_t)g_lists[e * NT + mrow] * ND + ah;
    const uint32_t adst = sb0 + (ar * 20 + ah) * 4;
    const int brr = tid >> 4;
    const int bcc = tid & 15;
    const float* bgsrc = Wg + (size_t)e * ND * NF + (size_t)brr * NF + n0 + bcc * 4;
    const float* busrc = Wu + (size_t)e * ND * NF + (size_t)brr * NF + n0 + bcc * 4;
    const uint32_t bgdst = sb0 + (GU_AF + brr * 72 + bcc * 4) * 4;
    const uint32_t budst = sb0 + (GU_AF + GU_BF + brr * 72 + bcc * 4) * 4;

    float accG[2][4][4], accU[2][4][4];
    #pragma unroll
    for (int i = 0; i < 2; i++)
        #pragma unroll
        for (int j = 0; j < 4; j++)
            #pragma unroll
            for (int k = 0; k < 4; k++) { accG[i][j][k] = 0.f; accU[i][j][k] = 0.f; }

    const int KT = ND / 16;    // 128
    auto issue = [&](int it) {
        const uint32_t so = (uint32_t)(it % 5) * (GU_STAGEF * 4);
        const size_t ka = (size_t)it * 16;
        cpa16(adst + so,      asrc + ka);
        cpa16(adst + so + 16, asrc + ka + 4);
        cpa16(bgdst + so, bgsrc + ka * NF);
        cpa16(budst + so, busrc + ka * NF);
    };

    issue(0); cpa_commit();
    issue(1); cpa_commit();
    issue(2); cpa_commit();
    issue(3); cpa_commit();

    // ldmatrix lane offset (bytes): rows (wm*32 + (lane&15)), k-offset (lane>=16)*4
    const uint32_t aldm = ((wm * 32 + (lane & 15)) * 20 + ((lane >> 4) << 2)) * 4;

    for (int it = 0; it < KT; ++it) {
        cpa_wait3();               // groups {it..it+3} pending -> group it complete
        __syncthreads();           // all warps past stage it-1 before overwrite
        if (it + 4 < KT) issue(it + 4);
        cpa_commit();

        const uint32_t sA = sb0 + (uint32_t)(it % 5) * (GU_STAGEF * 4);
        const float* Bg = smem + (it % 5) * GU_STAGEF + GU_AF;
        const float* Bu = Bg + GU_BF;

        #pragma unroll
        for (int ks = 0; ks < 16; ks += 8) {
            unsigned a[2][4];
            #pragma unroll
            for (int mi = 0; mi < 2; mi++)
                ldmA(a[mi], sA + aldm + (mi * 16 * 20 + ks) * 4);
            #pragma unroll
            for (int ni = 0; ni < 4; ni++) {
                const int nb = wn * 32 + ni * 8 + g4;
                unsigned bg[2] = { f2tf(Bg[(ks + t4) * 72 + nb]),
                                   f2tf(Bg[(ks + t4 + 4) * 72 + nb]) };
                unsigned bu[2] = { f2tf(Bu[(ks + t4) * 72 + nb]),
                                   f2tf(Bu[(ks + t4 + 4) * 72 + nb]) };
                #pragma unroll
                for (int mi = 0; mi < 2; mi++) {
                    mma8(accG[mi][ni], a[mi], bg);
                    mma8(accU[mi][ni], a[mi], bu);
                }
            }
        }
    }

    // epilogue: H = tf32( silu(G)*U )
    #pragma unroll
    for (int mi = 0; mi < 2; mi++) {
        #pragma unroll
        for (int half = 0; half < 2; half++) {
            const int m = m0 + wm * 32 + mi * 16 + g4 + half * 8;
            if (m >= Me) continue;
            float* Hrow = g_H + ((size_t)e * NT + m) * NF + n0 + wn * 32;
            #pragma unroll
            for (int ni = 0; ni < 4; ni++) {
                float gv0 = accG[mi][ni][half * 2],     uv0 = accU[mi][ni][half * 2];
                float gv1 = accG[mi][ni][half * 2 + 1], uv1 = accU[mi][ni][half * 2 + 1];
                float h0 = tf32r(gv0 / (1.f + expf(-gv0)) * uv0);
                float h1 = tf32r(gv1 / (1.f + expf(-gv1)) * uv1);
                *(float2*)(Hrow + ni * 8 + 2 * t4) = make_float2(h0, h1);
            }
        }
    }
}

// ---------------------------------------------------------------------------
// DOWN GEMM + combine (tf32 mma.sync, cp.async 5-stage pipeline, 256 thr, 2 CTA/SM)
// Block tile 128x128x16. 8 warps 4x2 -> 32x64 warptile.
// A row stride 20 (ldmatrix); B row stride 136.
// ---------------------------------------------------------------------------
#define DN_AF 2560          // 128*20
#define DN_BF 2176          // 16*136
#define DN_STAGEF (DN_AF + DN_BF)             // 4736 floats = 18944 B
#define DN_SMEM (5 * DN_STAGEF * 4)           // 94720 B

__global__ __launch_bounds__(256, 2) void down_tc(const float* __restrict__ Wd,
                                                  float* __restrict__ OUT) {
    const int e  = blockIdx.z;
    const int Me = g_counts[e];
    const int m0 = blockIdx.x * 128;
    if (m0 >= Me) return;
    const int n0 = blockIdx.y * 128;

    extern __shared__ float smem[];
    const uint32_t sb0 = smem_u32(smem);

    const int tid  = threadIdx.x;
    const int warp = tid >> 5;
    const int lane = tid & 31;
    const int g4   = lane >> 2;
    const int t4   = lane & 3;
    const int wm   = warp >> 1;
    const int wn   = warp & 1;

    const int ar = tid >> 1;
    const int ah = (tid & 1) * 8;
    const float* asrc = g_H + ((size_t)e * NT + m0 + ar) * NF + ah;  // rows>=Me read zeros
    const uint32_t adst = sb0 + (ar * 20 + ah) * 4;

    const int br0 = tid >> 5, bc0 = tid & 31;
    const float* bsrc = Wd + (size_t)e * NF * ND + n0;
    const uint32_t bbase = sb0 + DN_AF * 4;

    float acc[2][8][4];
    #pragma unroll
    for (int i = 0; i < 2; i++)
        #pragma unroll
        for (int j = 0; j < 8; j++)
            #pragma unroll
            for (int k = 0; k < 4; k++) acc[i][j][k] = 0.f;

    const int KT = NF / 16;   // 512
    auto issue = [&](int it) {
        const uint32_t so = (uint32_t)(it % 5) * (DN_STAGEF * 4);
        const size_t ka = (size_t)it * 16;
        cpa16(adst + so,      asrc + ka);
        cpa16(adst + so + 16, asrc + ka + 4);
        #pragma unroll
        for (int j = 0; j < 2; j++) {
            const int row = br0 + j * 8;
            cpa16(bbase + so + (row * 136 + bc0 * 4) * 4, bsrc + (ka + row) * ND + bc0 * 4);
        }
    };

    issue(0); cpa_commit();
    issue(1); cpa_commit();
    issue(2); cpa_commit();
    issue(3); cpa_commit();

    const uint32_t aldm = ((wm * 32 + (lane & 15)) * 20 + ((lane >> 4) << 2)) * 4;

    for (int it = 0; it < KT; ++it) {
        cpa_wait3();
        __syncthreads();
        if (it + 4 < KT) issue(it + 4);
        cpa_commit();

        const uint32_t sA = sb0 + (uint32_t)(it % 5) * (DN_STAGEF * 4);
        const float* Bs = smem + (it % 5) * DN_STAGEF + DN_AF;

        #pragma unroll
        for (int ks = 0; ks < 16; ks += 8) {
            unsigned a[2][4];
            #pragma unroll
            for (int mi = 0; mi < 2; mi++)
                ldmA(a[mi], sA + aldm + (mi * 16 * 20 + ks) * 4);
            #pragma unroll
            for (int ni = 0; ni < 8; ni++) {
                const int nb = wn * 64 + ni * 8 + g4;
                unsigned b[2] = { f2tf(Bs[(ks + t4) * 136 + nb]),
                                  f2tf(Bs[(ks + t4 + 4) * 136 + nb]) };
                #pragma unroll
                for (int mi = 0; mi < 2; mi++)
                    mma8(acc[mi][ni], a[mi], b);
            }
        }
    }

    #pragma unroll
    for (int mi = 0; mi < 2; mi++) {
        #pragma unroll
        for (int half = 0; half < 2; half++) {
            const int m = m0 + wm * 32 + mi * 16 + g4 + half * 8;
            if (m >= Me) continue;
            const int tok = g_lists[e * NT + m];
            const float w = g_gatew[e * NT + tok];
            float* dst = OUT + (size_t)tok * ND + n0 + wn * 64;
            #pragma unroll
            for (int ni = 0; ni < 8; ni++) {
                atomicAdd(dst + ni * 8 + 2 * t4,     w * acc[mi][ni][half * 2]);
                atomicAdd(dst + ni * 8 + 2 * t4 + 1, w * acc[mi][ni][half * 2 + 1]);
            }
        }
    }
}

// ---------------------------------------------------------------------------
extern "C" void kernel_launch(void* const* d_in, const int* in_sizes, int n_in,
                              void* d_out, int out_size) {
    const float* x  = (const float*)d_in[0];
    const float* Wr = (const float*)d_in[1];
    const float* Wg = (const float*)d_in[2];
    const float* Wu = (const float*)d_in[3];
    const float* Wd = (const float*)d_in[4];
    float* out = (float*)d_out;

    cudaFuncSetAttribute(gateup_tc, cudaFuncAttributeMaxDynamicSharedMemorySize, GU_SMEM);
    cudaFuncSetAttribute(down_tc,   cudaFuncAttributeMaxDynamicSharedMemorySize, DN_SMEM);

    float* xr;  cudaGetSymbolAddress((void**)&xr, g_Xr);

    // launch order puts gateup_tc at index 3 (the slot ncu profiles)
    prep_kernel<<<2048, 256>>>(x, xr, out);                          // 0
    router_kernel<<<NT, 256>>>(x, Wr);                               // 1
    compact_kernel<<<1, 256>>>();                                    // 2
    gateup_tc<<<dim3(NT/128, NF/64, NE), 256, GU_SMEM>>>(xr, Wg, Wu); // 3
    down_tc  <<<dim3(NT/128, ND/128, NE), 256, DN_SMEM>>>(Wd, out);  // 4
}

// round 11
// speedup vs baseline: 1.0632x; 1.0048x over previous
#include <cuda_runtime.h>
#include <math.h>
#include <stdint.h>

#define NB 2
#define NS 1024
#define NT (NB*NS)      // 2048 tokens
#define ND 2048
#define NF 8192
#define NE 4

// ---------------- persistent scratch (device globals) ----------------------
__device__ float g_gatew[NE*NT];
__device__ int   g_counts[NE];
__device__ int   g_lists[NE*NT];
__device__ float g_H [(size_t)NE*NT*NF];   // H = silu(G)*U, tf32-rounded; rows >= Me stay 0
__device__ float g_Xr[(size_t)NT*ND];      // x, tf32-rounded

// ---------------- helpers ---------------------------------------------------
__device__ __forceinline__ uint32_t smem_u32(const void* p) {
    uint32_t a;
    asm("{ .reg .u64 t; cvta.to.shared.u64 t, %1; cvt.u32.u64 %0, t; }" : "=r"(a) : "l"(p));
    return a;
}
__device__ __forceinline__ unsigned f2tf(float f) {
    unsigned u; asm("cvt.rna.tf32.f32 %0, %1;" : "=r"(u) : "f"(f)); return u;
}
__device__ __forceinline__ float tf32r(float f) { return __uint_as_float(f2tf(f)); }

__device__ __forceinline__ void cpa16(uint32_t dst, const float* src) {
    asm volatile("cp.async.cg.shared.global [%0], [%1], 16;" :: "r"(dst), "l"(src));
}
__device__ __forceinline__ void cpa_commit() { asm volatile("cp.async.commit_group;"); }
__device__ __forceinline__ void cpa_wait2()  { asm volatile("cp.async.wait_group 2;"); }

__device__ __forceinline__ void mma8(float c[4], const unsigned a[4], const unsigned b[2]) {
    asm volatile(
        "mma.sync.aligned.m16n8k8.row.col.f32.tf32.tf32.f32 "
        "{%0,%1,%2,%3}, {%4,%5,%6,%7}, {%8,%9}, {%0,%1,%2,%3};"
        : "+f"(c[0]), "+f"(c[1]), "+f"(c[2]), "+f"(c[3])
        : "r"(a[0]), "r"(a[1]), "r"(a[2]), "r"(a[3]), "r"(b[0]), "r"(b[1]));
}
// ldmatrix x4 on the stride-20 A tile (lane mapping validated: bit-identical results)
__device__ __forceinline__ void ldmA(unsigned r[4], uint32_t addr) {
    asm volatile("ldmatrix.sync.aligned.m8n8.x4.shared.b16 {%0,%1,%2,%3}, [%4];"
        : "=r"(r[0]), "=r"(r[1]), "=r"(r[2]), "=r"(r[3]) : "r"(addr));
}

// ---------------- prep: zero output + counts, round x -> tf32 ---------------
__global__ void prep_kernel(const float* __restrict__ x, float* __restrict__ xr,
                            float* __restrict__ out) {
    const size_t n4 = (size_t)NT * ND / 4;
    const float4 z = make_float4(0.f, 0.f, 0.f, 0.f);
    for (size_t i = blockIdx.x * (size_t)blockDim.x + threadIdx.x; i < n4;
         i += (size_t)gridDim.x * blockDim.x) {
        ((float4*)out)[i] = z;
        float4 v = ((const float4*)x)[i];
        ((float4*)xr)[i] = make_float4(tf32r(v.x), tf32r(v.y), tf32r(v.z), tf32r(v.w));
    }
    if (blockIdx.x == 0 && threadIdx.x < NE) g_counts[threadIdx.x] = 0;
}

__global__ void router_kernel(const float* __restrict__ x, const float* __restrict__ Wr) {
    int t = blockIdx.x;
    const float* xr = x + (size_t)t * ND;
    float acc[NE] = {0.f, 0.f, 0.f, 0.f};
    for (int d = threadIdx.x; d < ND; d += blockDim.x) {
        float xv = xr[d];
        float4 w = *(const float4*)(Wr + d * NE);
        acc[0] += xv * w.x; acc[1] += xv * w.y; acc[2] += xv * w.z; acc[3] += xv * w.w;
    }
    __shared__ float sred[NE][8];
    int lane = threadIdx.x & 31, wid = threadIdx.x >> 5;
    #pragma unroll
    for (int e = 0; e < NE; e++) {
        float s = acc[e];
        #pragma unroll
        for (int off = 16; off > 0; off >>= 1) s += __shfl_down_sync(0xffffffffu, s, off);
        if (lane == 0) sred[e][wid] = s;
    }
    __syncthreads();
    if (threadIdx.x == 0) {
        float l[NE];
        #pragma unroll
        for (int e = 0; e < NE; e++) {
            float s = 0.f;
            #pragma unroll
            for (int w = 0; w < 8; w++) s += sred[e][w];
            l[e] = s;
        }
        float mx = fmaxf(fmaxf(l[0], l[1]), fmaxf(l[2], l[3]));
        float ex[NE], ssum = 0.f;
        #pragma unroll
        for (int e = 0; e < NE; e++) { ex[e] = expf(l[e] - mx); ssum += ex[e]; }
        float p[NE];
        #pragma unroll
        for (int e = 0; e < NE; e++) p[e] = ex[e] / ssum;
        int i1 = 0;
        #pragma unroll
        for (int e = 1; e < NE; e++) if (p[e] > p[i1]) i1 = e;
        int i2 = -1;
        #pragma unroll
        for (int e = 0; e < NE; e++)
            if (e != i1 && (i2 < 0 || p[e] > p[i2])) i2 = e;
        #pragma unroll
        for (int e = 0; e < NE; e++)
            g_gatew[e * NT + t] = (e == i1 || e == i2) ? p[e] : 0.f;
    }
}

__global__ void compact_kernel() {
    for (int t = threadIdx.x; t < NT; t += blockDim.x) {
        #pragma unroll
        for (int e = 0; e < NE; e++) {
            if (g_gatew[e * NT + t] > 0.f) {
                int p = atomicAdd(&g_counts[e], 1);
                g_lists[e * NT + p] = t;
            }
        }
    }
}

// ---------------------------------------------------------------------------
// GATE+UP fused GEMM (tf32 mma.sync, cp.async 4-stage, 256 thr, 2 CTA/SM)
// Block tile M=128, N=64 per matrix, K=16.
// Warp grid 2(M) x 4(N): warptile 64x32.  wn<2 -> G warp, wn>=2 -> U warp.
// A: [128][16k] row stride 20 words (ldmatrix).  Bg/Bu: [16k][64n] stride 72.
// Epilogue: U warps stash to smem; G warps write H = tf32(silu(G)*U).
// ---------------------------------------------------------------------------
#define GU_AF 2560          // 128*20 floats
#define GU_BF 1152          // 16*72 floats
#define GU_STAGEF (GU_AF + 2*GU_BF)           // 4864 floats = 19456 B
#define GU_SMEM (4 * GU_STAGEF * 4)           // 77824 B (Us 128*68*4=34816 aliases)

__global__ __launch_bounds__(256, 2) void gateup_tc(const float* __restrict__ X,
                                                    const float* __restrict__ Wg,
                                                    const float* __restrict__ Wu) {
    const int e  = blockIdx.z;
    const int Me = g_counts[e];
    const int m0 = blockIdx.x * 128;
    if (m0 >= Me) return;
    const int n0 = blockIdx.y * 64;

    extern __shared__ float smem[];
    const uint32_t sb0 = smem_u32(smem);

    const int tid  = threadIdx.x;
    const int warp = tid >> 5;
    const int lane = tid & 31;
    const int g4   = lane >> 2;
    const int t4   = lane & 3;
    const int wm   = warp >> 2;        // 0..1  (64-row half)
    const int wn   = warp & 3;         // 0..3
    const int mat  = wn >> 1;          // 0=G, 1=U
    const int hn   = wn & 1;           // 32-col half within matrix

    const int ar = tid >> 1;
    const int ah = (tid & 1) * 8;
    int mrow = m0 + ar; if (mrow >= Me) mrow = Me - 1;
    const float* asrc = X + (size_t)g_lists[e * NT + mrow] * ND + ah;
    const uint32_t adst = sb0 + (ar * 20 + ah) * 4;
    const int brr = tid >> 4;
    const int bcc = tid & 15;
    const float* bgsrc = Wg + (size_t)e * ND * NF + (size_t)brr * NF + n0 + bcc * 4;
    const float* busrc = Wu + (size_t)e * ND * NF + (size_t)brr * NF + n0 + bcc * 4;
    const uint32_t bgdst = sb0 + (GU_AF + brr * 72 + bcc * 4) * 4;
    const uint32_t budst = sb0 + (GU_AF + GU_BF + brr * 72 + bcc * 4) * 4;

    float acc[4][4][4];
    #pragma unroll
    for (int i = 0; i < 4; i++)
        #pragma unroll
        for (int j = 0; j < 4; j++)
            #pragma unroll
            for (int k = 0; k < 4; k++) acc[i][j][k] = 0.f;

    const int KT = ND / 16;    // 128
    auto issue = [&](int it) {
        const uint32_t so = (uint32_t)(it & 3) * (GU_STAGEF * 4);
        const size_t ka = (size_t)it * 16;
        cpa16(adst + so,      asrc + ka);
        cpa16(adst + so + 16, asrc + ka + 4);
        cpa16(bgdst + so, bgsrc + ka * NF);
        cpa16(budst + so, busrc + ka * NF);
    };

    issue(0); cpa_commit();
    issue(1); cpa_commit();
    issue(2); cpa_commit();

    // ldmatrix base: rows (wm*64 + (lane&15)), k-offset (lane>=16)*4
    const uint32_t aldm = ((wm * 64 + (lane & 15)) * 20 + ((lane >> 4) << 2)) * 4;
    const int bbw = GU_AF + mat * GU_BF;       // this warp's B matrix (word offset)

    for (int it = 0; it < KT; ++it) {
        cpa_wait2();               // groups {it..it+2} pending -> group it complete
        __syncthreads();
        if (it + 3 < KT) issue(it + 3);
        cpa_commit();

        const uint32_t sA = sb0 + (uint32_t)(it & 3) * (GU_STAGEF * 4);
        const float* Bm = smem + (it & 3) * GU_STAGEF + bbw;

        #pragma unroll
        for (int ks = 0; ks < 16; ks += 8) {
            unsigned a[4][4];
            #pragma unroll
            for (int mi = 0; mi < 4; mi++)
                ldmA(a[mi], sA + aldm + (mi * 16 * 20 + ks) * 4);
            #pragma unroll
            for (int ni = 0; ni < 4; ni++) {
                const int nb = hn * 32 + ni * 8 + g4;
                unsigned b[2] = { f2tf(Bm[(ks + t4) * 72 + nb]),
                                  f2tf(Bm[(ks + t4 + 4) * 72 + nb]) };
                #pragma unroll
                for (int mi = 0; mi < 4; mi++)
                    mma8(acc[mi][ni], a[mi], b);
            }
        }
    }

    // ---- epilogue: U warps stash via smem; G warps write H = tf32(silu(G)*U) ----
    __syncthreads();                  // mainloop fully consumed; reuse stages as Us[128][68]
    float* Us = smem;
    if (mat == 1) {
        #pragma unroll
        for (int mi = 0; mi < 4; mi++)
            #pragma unroll
            for (int half = 0; half < 2; half++) {
                const int ml = wm * 64 + mi * 16 + g4 + half * 8;
                #pragma unroll
                for (int ni = 0; ni < 4; ni++) {
                    const int col = hn * 32 + ni * 8 + 2 * t4;
                    *(float2*)(Us + ml * 68 + col) =
                        make_float2(acc[mi][ni][half * 2], acc[mi][ni][half * 2 + 1]);
                }
            }
    }
    __syncthreads();
    if (mat == 0) {
        #pragma unroll
        for (int mi = 0; mi < 4; mi++)
            #pragma unroll
            for (int half = 0; half < 2; half++) {
                const int ml = wm * 64 + mi * 16 + g4 + half * 8;
                const int m  = m0 + ml;
                if (m >= Me) continue;
                float* Hrow = g_H + ((size_t)e * NT + m) * NF + n0;
                #pragma unroll
                for (int ni = 0; ni < 4; ni++) {
                    const int col = hn * 32 + ni * 8 + 2 * t4;
                    float2 u = *(const float2*)(Us + ml * 68 + col);
                    float gv0 = acc[mi][ni][half * 2], gv1 = acc[mi][ni][half * 2 + 1];
                    float h0 = tf32r(gv0 / (1.f + expf(-gv0)) * u.x);
                    float h1 = tf32r(gv1 / (1.f + expf(-gv1)) * u.y);
                    *(float2*)(Hrow + col) = make_float2(h0, h1);
                }
            }
    }
}

// ---------------------------------------------------------------------------
// DOWN GEMM + combine (tf32 mma.sync, cp.async 4-stage, 256 thr, 2 CTA/SM)
// Block tile 128x128x16.  Warp grid 2(M) x 4(N): warptile 64x32.
// A: [128][16] stride 20 (ldmatrix); B: [16][128] stride 136.
// ---------------------------------------------------------------------------
#define DN_AF 2560          // 128*20
#define DN_BF 2176          // 16*136
#define DN_STAGEF (DN_AF + DN_BF)             // 4736 floats = 18944 B
#define DN_SMEM (4 * DN_STAGEF * 4)           // 75776 B

__global__ __launch_bounds__(256, 2) void down_tc(const float* __restrict__ Wd,
                                                  float* __restrict__ OUT) {
    const int e  = blockIdx.z;
    const int Me = g_counts[e];
    const int m0 = blockIdx.x * 128;
    if (m0 >= Me) return;
    const int n0 = blockIdx.y * 128;

    extern __shared__ float smem[];
    const uint32_t sb0 = smem_u32(smem);

    const int tid  = threadIdx.x;
    const int warp = tid >> 5;
    const int lane = tid & 31;
    const int g4   = lane >> 2;
    const int t4   = lane & 3;
    const int wm   = warp >> 2;        // 0..1
    const int wn   = warp & 3;         // 0..3

    const int ar = tid >> 1;
    const int ah = (tid & 1) * 8;
    const float* asrc = g_H + ((size_t)e * NT + m0 + ar) * NF + ah;  // rows>=Me read zeros
    const uint32_t adst = sb0 + (ar * 20 + ah) * 4;

    const int br0 = tid >> 5, bc0 = tid & 31;
    const float* bsrc = Wd + (size_t)e * NF * ND + n0;
    const uint32_t bbase = sb0 + DN_AF * 4;

    float acc[4][4][4];
    #pragma unroll
    for (int i = 0; i < 4; i++)
        #pragma unroll
        for (int j = 0; j < 4; j++)
            #pragma unroll
            for (int k = 0; k < 4; k++) acc[i][j][k] = 0.f;

    const int KT = NF / 16;   // 512
    auto issue = [&](int it) {
        const uint32_t so = (uint32_t)(it & 3) * (DN_STAGEF * 4);
        const size_t ka = (size_t)it * 16;
        cpa16(adst + so,      asrc + ka);
        cpa16(adst + so + 16, asrc + ka + 4);
        #pragma unroll
        for (int j = 0; j < 2; j++) {
            const int row = br0 + j * 8;
            cpa16(bbase + so + (row * 136 + bc0 * 4) * 4, bsrc + (ka + row) * ND + bc0 * 4);
        }
    };

    issue(0); cpa_commit();
    issue(1); cpa_commit();
    issue(2); cpa_commit();

    const uint32_t aldm = ((wm * 64 + (lane & 15)) * 20 + ((lane >> 4) << 2)) * 4;

    for (int it = 0; it < KT; ++it) {
        cpa_wait2();
        __syncthreads();
        if (it + 3 < KT) issue(it + 3);
        cpa_commit();

        const uint32_t sA = sb0 + (uint32_t)(it & 3) * (DN_STAGEF * 4);
        const float* Bs = smem + (it & 3) * DN_STAGEF + DN_AF;

        #pragma unroll
        for (int ks = 0; ks < 16; ks += 8) {
            unsigned a[4][4];
            #pragma unroll
            for (int mi = 0; mi < 4; mi++)
                ldmA(a[mi], sA + aldm + (mi * 16 * 20 + ks) * 4);
            #pragma unroll
            for (int ni = 0; ni < 4; ni++) {
                const int nb = wn * 32 + ni * 8 + g4;
                unsigned b[2] = { f2tf(Bs[(ks + t4) * 136 + nb]),
                                  f2tf(Bs[(ks + t4 + 4) * 136 + nb]) };
                #pragma unroll
                for (int mi = 0; mi < 4; mi++)
                    mma8(acc[mi][ni], a[mi], b);
            }
        }
    }

    #pragma unroll
    for (int mi = 0; mi < 4; mi++) {
        #pragma unroll
        for (int half = 0; half < 2; half++) {
            const int m = m0 + wm * 64 + mi * 16 + g4 + half * 8;
            if (m >= Me) continue;
            const int tok = g_lists[e * NT + m];
            const float w = g_gatew[e * NT + tok];
            float* dst = OUT + (size_t)tok * ND + n0 + wn * 32;
            #pragma unroll
            for (int ni = 0; ni < 4; ni++) {
                atomicAdd(dst + ni * 8 + 2 * t4,     w * acc[mi][ni][half * 2]);
                atomicAdd(dst + ni * 8 + 2 * t4 + 1, w * acc[mi][ni][half * 2 + 1]);
            }
        }
    }
}

// ---------------------------------------------------------------------------
extern "C" void kernel_launch(void* const* d_in, const int* in_sizes, int n_in,
                              void* d_out, int out_size) {
    const float* x  = (const float*)d_in[0];
    const float* Wr = (const float*)d_in[1];
    const float* Wg = (const float*)d_in[2];
    const float* Wu = (const float*)d_in[3];
    const float* Wd = (const float*)d_in[4];
    float* out = (float*)d_out;

    cudaFuncSetAttribute(gateup_tc, cudaFuncAttributeMaxDynamicSharedMemorySize, GU_SMEM);
    cudaFuncSetAttribute(down_tc,   cudaFuncAttributeMaxDynamicSharedMemorySize, DN_SMEM);

    float* xr;  cudaGetSymbolAddress((void**)&xr, g_Xr);

    // launch order keeps gateup_tc at index 3 (the slot ncu profiles)
    prep_kernel<<<2048, 256>>>(x, xr, out);                           // 0
    router_kernel<<<NT, 256>>>(x, Wr);                                // 1
    compact_kernel<<<1, 256>>>();                                     // 2
    gateup_tc<<<dim3(NT/128, NF/64, NE), 256, GU_SMEM>>>(xr, Wg, Wu); // 3
    down_tc  <<<dim3(NT/128, ND/128, NE), 256, DN_SMEM>>>(Wd, out);   // 4
}

// round 12
// speedup vs baseline: 1.9038x; 1.7906x over previous
#include <cuda_runtime.h>
#include <cuda_fp16.h>
#include <math.h>
#include <stdint.h>

#define NB 2
#define NS 1024
#define NT (NB*NS)      // 2048 tokens
#define ND 2048
#define NF 8192
#define NE 4

// ---------------- persistent scratch (device globals) ----------------------
__device__ float    g_gatew[NE*NT];
__device__ int      g_counts[NE];
__device__ int      g_lists[NE*NT];
__device__ __half   g_Xh[(size_t)NT*ND];            // x, fp16 (natural layout)
__device__ __half   g_Hh[(size_t)NE*NT*NF];         // H = silu(G)*U, fp16; rows >= Me stay 0
__device__ uint32_t g_Wgp[(size_t)NE*(ND/2)*NF];    // weights, fp16 k-pair packed [K/2][N]
__device__ uint32_t g_Wup[(size_t)NE*(ND/2)*NF];
__device__ uint32_t g_Wdp[(size_t)NE*(NF/2)*ND];

// ---------------- helpers ---------------------------------------------------
__device__ __forceinline__ uint32_t smem_u32(const void* p) {
    uint32_t a;
    asm("{ .reg .u64 t; cvta.to.shared.u64 t, %1; cvt.u32.u64 %0, t; }" : "=r"(a) : "l"(p));
    return a;
}
__device__ __forceinline__ uint32_t packh2(float lo, float hi) {
    __half2 h = __float22half2_rn(make_float2(lo, hi));   // lo -> low half (k even)
    return *reinterpret_cast<uint32_t*>(&h);
}
__device__ __forceinline__ void cpa16(uint32_t dst, const void* src) {
    asm volatile("cp.async.cg.shared.global [%0], [%1], 16;" :: "r"(dst), "l"(src));
}
__device__ __forceinline__ void cpa_commit() { asm volatile("cp.async.commit_group;"); }
__device__ __forceinline__ void cpa_wait2()  { asm volatile("cp.async.wait_group 2;"); }

__device__ __forceinline__ void mma16(float c[4], const unsigned a[4], const unsigned b[2]) {
    asm volatile(
        "mma.sync.aligned.m16n8k16.row.col.f32.f16.f16.f32 "
        "{%0,%1,%2,%3}, {%4,%5,%6,%7}, {%8,%9}, {%0,%1,%2,%3};"
        : "+f"(c[0]), "+f"(c[1]), "+f"(c[2]), "+f"(c[3])
        : "r"(a[0]), "r"(a[1]), "r"(a[2]), "r"(a[3]), "r"(b[0]), "r"(b[1]));
}
// ldmatrix x4 b16: lanes 0-15 -> rows 0-15 @k0, lanes 16-31 -> rows 0-15 @k8
__device__ __forceinline__ void ldmA(unsigned r[4], uint32_t addr) {
    asm volatile("ldmatrix.sync.aligned.m8n8.x4.shared.b16 {%0,%1,%2,%3}, [%4];"
        : "=r"(r[0]), "=r"(r[1]), "=r"(r[2]), "=r"(r[3]) : "r"(addr));
}

// ---------------- prep: zero out + counts, x -> fp16 ------------------------
__global__ void prep_kernel(const float* __restrict__ x, float* __restrict__ out) {
    const size_t n4 = (size_t)NT * ND / 4;
    const float4 z = make_float4(0.f, 0.f, 0.f, 0.f);
    for (size_t i = blockIdx.x * (size_t)blockDim.x + threadIdx.x; i < n4;
         i += (size_t)gridDim.x * blockDim.x) {
        ((float4*)out)[i] = z;
        float4 v = ((const float4*)x)[i];
        uint2 o;
        o.x = packh2(v.x, v.y);
        o.y = packh2(v.z, v.w);
        ((uint2*)g_Xh)[i] = o;
    }
    if (blockIdx.x == 0 && threadIdx.x < NE) g_counts[threadIdx.x] = 0;
}

// weights fp32 [R][C] -> fp16 k-pair packed [R/2][C] half2 words
__global__ void wpack_kernel(const float* __restrict__ src, uint32_t* __restrict__ dst,
                             int r2max, int c4max, int C) {
    const size_t total = (size_t)r2max * c4max;
    for (size_t idx = blockIdx.x * (size_t)blockDim.x + threadIdx.x; idx < total;
         idx += (size_t)gridDim.x * blockDim.x) {
        const size_t r2 = idx / c4max;
        const int    c  = (int)(idx % c4max);
        const float4 lo = *(const float4*)(src + (2*r2)     * C + c*4);
        const float4 hi = *(const float4*)(src + (2*r2 + 1) * C + c*4);
        uint4 o;
        o.x = packh2(lo.x, hi.x); o.y = packh2(lo.y, hi.y);
        o.z = packh2(lo.z, hi.z); o.w = packh2(lo.w, hi.w);
        *(uint4*)(dst + r2 * (size_t)C + c*4) = o;
    }
}

__global__ void router_kernel(const float* __restrict__ x, const float* __restrict__ Wr) {
    int t = blockIdx.x;
    const float* xr = x + (size_t)t * ND;
    float acc[NE] = {0.f, 0.f, 0.f, 0.f};
    for (int d = threadIdx.x; d < ND; d += blockDim.x) {
        float xv = xr[d];
        float4 w = *(const float4*)(Wr + d * NE);
        acc[0] += xv * w.x; acc[1] += xv * w.y; acc[2] += xv * w.z; acc[3] += xv * w.w;
    }
    __shared__ float sred[NE][8];
    int lane = threadIdx.x & 31, wid = threadIdx.x >> 5;
    #pragma unroll
    for (int e = 0; e < NE; e++) {
        float s = acc[e];
        #pragma unroll
        for (int off = 16; off > 0; off >>= 1) s += __shfl_down_sync(0xffffffffu, s, off);
        if (lane == 0) sred[e][wid] = s;
    }
    __syncthreads();
    if (threadIdx.x == 0) {
        float l[NE];
        #pragma unroll
        for (int e = 0; e < NE; e++) {
            float s = 0.f;
            #pragma unroll
            for (int w = 0; w < 8; w++) s += sred[e][w];
            l[e] = s;
        }
        float mx = fmaxf(fmaxf(l[0], l[1]), fmaxf(l[2], l[3]));
        float ex[NE], ssum = 0.f;
        #pragma unroll
        for (int e = 0; e < NE; e++) { ex[e] = expf(l[e] - mx); ssum += ex[e]; }
        float p[NE];
        #pragma unroll
        for (int e = 0; e < NE; e++) p[e] = ex[e] / ssum;
        int i1 = 0;
        #pragma unroll
        for (int e = 1; e < NE; e++) if (p[e] > p[i1]) i1 = e;
        int i2 = -1;
        #pragma unroll
        for (int e = 0; e < NE; e++)
            if (e != i1 && (i2 < 0 || p[e] > p[i2])) i2 = e;
        #pragma unroll
        for (int e = 0; e < NE; e++)
            g_gatew[e * NT + t] = (e == i1 || e == i2) ? p[e] : 0.f;
    }
}

__global__ void compact_kernel() {
    for (int t = threadIdx.x; t < NT; t += blockDim.x) {
        #pragma unroll
        for (int e = 0; e < NE; e++) {
            if (g_gatew[e * NT + t] > 0.f) {
                int p = atomicAdd(&g_counts[e], 1);
                g_lists[e * NT + p] = t;
            }
        }
    }
}

// ---------------------------------------------------------------------------
// GATE+UP fused GEMM (fp16 m16n8k16 mma, cp.async 4-stage, BK=32, 256 thr, 2 CTA/SM)
// Block tile M=128, N=64 per matrix.  Warp grid 2(M) x 4(N): warptile 64x32.
//   wn<2 -> G warp, wn>=2 -> U warp.
// A: [128 rows][32 k] fp16, row stride 40 halves (80B; ldmatrix conflict-free)
// Bg/Bu: [16 k2][64 n] half2 words, row stride 72 words (conflict-free)
// Epilogue: U warps stash via smem; G warps write Hh = fp16(silu(G)*U).
// ---------------------------------------------------------------------------
#define GU_AB 10240                      // A bytes (128*40*2)
#define GU_BB 4608                       // per-matrix B bytes (16*72*4)
#define GU_STAGE (GU_AB + 2*GU_BB)       // 19456 B
#define GU_SMEM (4 * GU_STAGE)           // 77824 B  (Us 128*68*4=34816 aliases)

__global__ __launch_bounds__(256, 2) void gateup_tc() {
    const int e  = blockIdx.z;
    const int Me = g_counts[e];
    const int m0 = blockIdx.x * 128;
    if (m0 >= Me) return;
    const int n0 = blockIdx.y * 64;

    extern __shared__ char smem[];
    const uint32_t sb0 = smem_u32(smem);

    const int tid  = threadIdx.x;
    const int warp = tid >> 5;
    const int lane = tid & 31;
    const int g4   = lane >> 2;
    const int t4   = lane & 3;
    const int wm   = warp >> 2;        // 0..1
    const int wn   = warp & 3;         // 0..3
    const int mat  = wn >> 1;          // 0=G, 1=U
    const int hn   = wn & 1;           // 32-col half

    // A staging: row = tid>>1, half-of-row = (tid&1)*16 halves; 2x16B
    const int ar  = tid >> 1;
    const int ahh = (tid & 1) * 16;
    int mrow = m0 + ar; if (mrow >= Me) mrow = Me - 1;
    const __half* asrc = g_Xh + (size_t)g_lists[e * NT + mrow] * ND + ahh;
    const uint32_t adst = sb0 + ar * 80 + ahh * 2;
    // B staging: one 16B chunk per thread per matrix: row = tid>>4, c4 = tid&15
    const int brr = tid >> 4;
    const int bcc = tid & 15;
    const uint32_t* bgsrc = g_Wgp + ((size_t)e * (ND/2) + brr) * NF + n0 + bcc * 4;
    const uint32_t* busrc = g_Wup + ((size_t)e * (ND/2) + brr) * NF + n0 + bcc * 4;
    const uint32_t bgdst = sb0 + GU_AB + brr * 288 + bcc * 16;
    const uint32_t budst = sb0 + GU_AB + GU_BB + brr * 288 + bcc * 16;

    float acc[4][4][4];
    #pragma unroll
    for (int i = 0; i < 4; i++)
        #pragma unroll
        for (int j = 0; j < 4; j++)
            #pragma unroll
            for (int k = 0; k < 4; k++) acc[i][j][k] = 0.f;

    const int KT = ND / 32;    // 64
    auto issue = [&](int it) {
        const uint32_t so  = (uint32_t)(it & 3) * GU_STAGE;
        const size_t   ka  = (size_t)it * 32;        // halves
        const size_t   ka2 = (size_t)it * 16;        // packed rows
        cpa16(adst + so,      asrc + ka);
        cpa16(adst + so + 16, asrc + ka + 8);
        cpa16(bgdst + so, bgsrc + ka2 * NF);
        cpa16(budst + so, busrc + ka2 * NF);
    };

    issue(0); cpa_commit();
    issue(1); cpa_commit();
    issue(2); cpa_commit();

    // ldmatrix base (bytes): rows (wm*64 + (lane&15)), k-offset (lane>=16)*8 halves
    const uint32_t aldm = ((wm * 64 + (lane & 15)) * 40 + ((lane >> 4) * 8)) * 2;
    const uint32_t bofs = GU_AB + mat * GU_BB;

    for (int it = 0; it < KT; ++it) {
        cpa_wait2();               // groups {it..it+2} pending -> group it complete
        __syncthreads();
        if (it + 3 < KT) issue(it + 3);
        cpa_commit();

        const uint32_t sA = sb0 + (uint32_t)(it & 3) * GU_STAGE;
        const uint32_t* Bw = (const uint32_t*)(smem + (it & 3) * GU_STAGE + bofs);

        #pragma unroll
        for (int s = 0; s < 2; s++) {          // two k16 slices per BK=32
            unsigned a[4][4];
            #pragma unroll
            for (int mi = 0; mi < 4; mi++)
                ldmA(a[mi], sA + aldm + mi * 1280 + s * 32);   // 16*40*2=1280; 16 halves=32B
            #pragma unroll
            for (int ni = 0; ni < 4; ni++) {
                const int nb = hn * 32 + ni * 8 + g4;
                unsigned b[2] = { Bw[(s * 8 + t4) * 72 + nb],
                                  Bw[(s * 8 + 4 + t4) * 72 + nb] };
                #pragma unroll
                for (int mi = 0; mi < 4; mi++)
                    mma16(acc[mi][ni], a[mi], b);
            }
        }
    }

    // ---- epilogue: U warps stash; G warps write Hh = fp16(silu(G)*U) ----
    __syncthreads();
    float* Us = (float*)smem;                  // [128][68]
    if (mat == 1) {
        #pragma unroll
        for (int mi = 0; mi < 4; mi++)
            #pragma unroll
            for (int half = 0; half < 2; half++) {
                const int ml = wm * 64 + mi * 16 + g4 + half * 8;
                #pragma unroll
                for (int ni = 0; ni < 4; ni++) {
                    const int col = hn * 32 + ni * 8 + 2 * t4;
                    *(float2*)(Us + ml * 68 + col) =
                        make_float2(acc[mi][ni][half * 2], acc[mi][ni][half * 2 + 1]);
                }
            }
    }
    __syncthreads();
    if (mat == 0) {
        #pragma unroll
        for (int mi = 0; mi < 4; mi++)
            #pragma unroll
            for (int half = 0; half < 2; half++) {
                const int ml = wm * 64 + mi * 16 + g4 + half * 8;
                const int m  = m0 + ml;
                if (m >= Me) continue;
                __half* Hrow = g_Hh + ((size_t)e * NT + m) * NF + n0;
                #pragma unroll
                for (int ni = 0; ni < 4; ni++) {
                    const int col = hn * 32 + ni * 8 + 2 * t4;
                    float2 u = *(const float2*)(Us + ml * 68 + col);
                    float gv0 = acc[mi][ni][half * 2], gv1 = acc[mi][ni][half * 2 + 1];
                    float h0 = gv0 / (1.f + expf(-gv0)) * u.x;
                    float h1 = gv1 / (1.f + expf(-gv1)) * u.y;
                    *(uint32_t*)(Hrow + col) = packh2(h0, h1);
                }
            }
    }
}

// ---------------------------------------------------------------------------
// DOWN GEMM + combine (fp16 m16n8k16 mma, cp.async 4-stage, BK=32, 256 thr, 2 CTA/SM)
// Block tile 128x128.  Warp grid 2(M) x 4(N): warptile 64x32.
// A: [128][32] fp16 stride 40 halves (ldmatrix); B: [16 k2][128 n] stride 136 words.
// ---------------------------------------------------------------------------
#define DN_AB 10240                      // 128*40*2
#define DN_BB 8704                       // 16*136*4
#define DN_STAGE (DN_AB + DN_BB)         // 18944 B
#define DN_SMEM (4 * DN_STAGE)           // 75776 B

__global__ __launch_bounds__(256, 2) void down_tc(float* __restrict__ OUT) {
    const int e  = blockIdx.z;
    const int Me = g_counts[e];
    const int m0 = blockIdx.x * 128;
    if (m0 >= Me) return;
    const int n0 = blockIdx.y * 128;

    extern __shared__ char smem[];
    const uint32_t sb0 = smem_u32(smem);

    const int tid  = threadIdx.x;
    const int warp = tid >> 5;
    const int lane = tid & 31;
    const int g4   = lane >> 2;
    const int t4   = lane & 3;
    const int wm   = warp >> 2;        // 0..1
    const int wn   = warp & 3;         // 0..3

    const int ar  = tid >> 1;
    const int ahh = (tid & 1) * 16;
    const __half* asrc = g_Hh + ((size_t)e * NT + m0 + ar) * NF + ahh;  // rows>=Me read zeros
    const uint32_t adst = sb0 + ar * 80 + ahh * 2;

    const uint32_t* bbase = g_Wdp + (size_t)e * (NF/2) * ND + n0;

    float acc[4][4][4];
    #pragma unroll
    for (int i = 0; i < 4; i++)
        #pragma unroll
        for (int j = 0; j < 4; j++)
            #pragma unroll
            for (int k = 0; k < 4; k++) acc[i][j][k] = 0.f;

    const int KT = NF / 32;   // 256
    auto issue = [&](int it) {
        const uint32_t so  = (uint32_t)(it & 3) * DN_STAGE;
        const size_t   ka  = (size_t)it * 32;
        const size_t   ka2 = (size_t)it * 16;
        cpa16(adst + so,      asrc + ka);
        cpa16(adst + so + 16, asrc + ka + 8);
        #pragma unroll
        for (int j = 0; j < 2; j++) {
            const int c = j * 256 + tid;
            const int row = c >> 5, c4 = c & 31;
            cpa16(sb0 + so + DN_AB + row * 544 + c4 * 16,
                  bbase + (ka2 + row) * ND + c4 * 4);
        }
    };

    issue(0); cpa_commit();
    issue(1); cpa_commit();
    issue(2); cpa_commit();

    const uint32_t aldm = ((wm * 64 + (lane & 15)) * 40 + ((lane >> 4) * 8)) * 2;

    for (int it = 0; it < KT; ++it) {
        cpa_wait2();
        __syncthreads();
        if (it + 3 < KT) issue(it + 3);
        cpa_commit();

        const uint32_t sA = sb0 + (uint32_t)(it & 3) * DN_STAGE;
        const uint32_t* Bw = (const uint32_t*)(smem + (it & 3) * DN_STAGE + DN_AB);

        #pragma unroll
        for (int s = 0; s < 2; s++) {
            unsigned a[4][4];
            #pragma unroll
            for (int mi = 0; mi < 4; mi++)
                ldmA(a[mi], sA + aldm + mi * 1280 + s * 32);
            #pragma unroll
            for (int ni = 0; ni < 4; ni++) {
                const int nb = wn * 32 + ni * 8 + g4;
                unsigned b[2] = { Bw[(s * 8 + t4) * 136 + nb],
                                  Bw[(s * 8 + 4 + t4) * 136 + nb] };
                #pragma unroll
                for (int mi = 0; mi < 4; mi++)
                    mma16(acc[mi][ni], a[mi], b);
            }
        }
    }

    #pragma unroll
    for (int mi = 0; mi < 4; mi++) {
        #pragma unroll
        for (int half = 0; half < 2; half++) {
            const int m = m0 + wm * 64 + mi * 16 + g4 + half * 8;
            if (m >= Me) continue;
            const int tok = g_lists[e * NT + m];
            const float w = g_gatew[e * NT + tok];
            float* dst = OUT + (size_t)tok * ND + n0 + wn * 32;
            #pragma unroll
            for (int ni = 0; ni < 4; ni++) {
                atomicAdd(dst + ni * 8 + 2 * t4,     w * acc[mi][ni][half * 2]);
                atomicAdd(dst + ni * 8 + 2 * t4 + 1, w * acc[mi][ni][half * 2 + 1]);
            }
        }
    }
}

// ---------------------------------------------------------------------------
extern "C" void kernel_launch(void* const* d_in, const int* in_sizes, int n_in,
                              void* d_out, int out_size) {
    const float* x  = (const float*)d_in[0];
    const float* Wr = (const float*)d_in[1];
    const float* Wg = (const float*)d_in[2];
    const float* Wu = (const float*)d_in[3];
    const float* Wd = (const float*)d_in[4];
    float* out = (float*)d_out;

    cudaFuncSetAttribute(gateup_tc, cudaFuncAttributeMaxDynamicSharedMemorySize, GU_SMEM);
    cudaFuncSetAttribute(down_tc,   cudaFuncAttributeMaxDynamicSharedMemorySize, DN_SMEM);

    uint32_t *wgp, *wup, *wdp;
    cudaGetSymbolAddress((void**)&wgp, g_Wgp);
    cudaGetSymbolAddress((void**)&wup, g_Wup);
    cudaGetSymbolAddress((void**)&wdp, g_Wdp);

    prep_kernel<<<2048, 256>>>(x, out);
    router_kernel<<<NT, 256>>>(x, Wr);
    compact_kernel<<<1, 256>>>();
    wpack_kernel<<<4096, 256>>>(Wg, wgp, NE*ND/2, NF/4, NF);
    wpack_kernel<<<4096, 256>>>(Wu, wup, NE*ND/2, NF/4, NF);
    wpack_kernel<<<4096, 256>>>(Wd, wdp, NE*NF/2, ND/4, ND);

    gateup_tc<<<dim3(NT/128, NF/64, NE), 256, GU_SMEM>>>();
    down_tc  <<<dim3(NT/128, ND/128, NE), 256, DN_SMEM>>>(out);
}

// round 13
// speedup vs baseline: 2.0496x; 1.0766x over previous
#include <cuda_runtime.h>
#include <cuda_fp16.h>
#include <math.h>
#include <stdint.h>

#define NB 2
#define NS 1024
#define NT (NB*NS)      // 2048 tokens
#define ND 2048
#define NF 8192
#define NE 4

// ---------------- persistent scratch (device globals) ----------------------
__device__ float    g_gatew[NE*NT];
__device__ int      g_counts[NE];
__device__ int      g_lists[NE*NT];
__device__ __half   g_Xh[(size_t)NT*ND];          // x, fp16 (k-contiguous rows)
__device__ __half   g_Hh[(size_t)NE*NT*NF];       // H = silu(G)*U fp16; rows >= Me stay 0
__device__ __half   g_WgT[(size_t)NE*NF*ND];      // Wg^T fp16 [E][N=F][K=D]
__device__ __half   g_WuT[(size_t)NE*NF*ND];      // Wu^T fp16 [E][N=F][K=D]
__device__ __half   g_WdT[(size_t)NE*ND*NF];      // Wd^T fp16 [E][N=D][K=F]

// ---------------- helpers ---------------------------------------------------
__device__ __forceinline__ uint32_t smem_u32(const void* p) {
    uint32_t a;
    asm("{ .reg .u64 t; cvta.to.shared.u64 t, %1; cvt.u32.u64 %0, t; }" : "=r"(a) : "l"(p));
    return a;
}
__device__ __forceinline__ uint32_t packh2(float lo, float hi) {
    __half2 h = __float22half2_rn(make_float2(lo, hi));   // lo -> low half (lower k)
    return *reinterpret_cast<uint32_t*>(&h);
}
__device__ __forceinline__ void cpa16(uint32_t dst, const void* src) {
    asm volatile("cp.async.cg.shared.global [%0], [%1], 16;" :: "r"(dst), "l"(src));
}
__device__ __forceinline__ void cpa_commit() { asm volatile("cp.async.commit_group;"); }
__device__ __forceinline__ void cpa_wait2()  { asm volatile("cp.async.wait_group 2;"); }

__device__ __forceinline__ void mma16(float c[4], const unsigned a[4],
                                      unsigned b0, unsigned b1) {
    asm volatile(
        "mma.sync.aligned.m16n8k16.row.col.f32.f16.f16.f32 "
        "{%0,%1,%2,%3}, {%4,%5,%6,%7}, {%8,%9}, {%0,%1,%2,%3};"
        : "+f"(c[0]), "+f"(c[1]), "+f"(c[2]), "+f"(c[3])
        : "r"(a[0]), "r"(a[1]), "r"(a[2]), "r"(a[3]), "r"(b0), "r"(b1));
}
__device__ __forceinline__ void ldm4(unsigned r[4], uint32_t addr) {
    asm volatile("ldmatrix.sync.aligned.m8n8.x4.shared.b16 {%0,%1,%2,%3}, [%4];"
        : "=r"(r[0]), "=r"(r[1]), "=r"(r[2]), "=r"(r[3]) : "r"(addr));
}

// ---------------- prep: zero out + counts, x -> fp16 ------------------------
__global__ void prep_kernel(const float* __restrict__ x, float* __restrict__ out) {
    const size_t n4 = (size_t)NT * ND / 4;
    const float4 z = make_float4(0.f, 0.f, 0.f, 0.f);
    for (size_t i = blockIdx.x * (size_t)blockDim.x + threadIdx.x; i < n4;
         i += (size_t)gridDim.x * blockDim.x) {
        ((float4*)out)[i] = z;
        float4 v = ((const float4*)x)[i];
        uint2 o;
        o.x = packh2(v.x, v.y);
        o.y = packh2(v.z, v.w);
        ((uint2*)g_Xh)[i] = o;
    }
    if (blockIdx.x == 0 && threadIdx.x < NE) g_counts[threadIdx.x] = 0;
}

// ---------------- router (+ fused compaction) -------------------------------
__global__ void router_kernel(const float* __restrict__ x, const float* __restrict__ Wr) {
    int t = blockIdx.x;
    const float* xr = x + (size_t)t * ND;
    float acc[NE] = {0.f, 0.f, 0.f, 0.f};
    for (int d = threadIdx.x; d < ND; d += blockDim.x) {
        float xv = xr[d];
        float4 w = *(const float4*)(Wr + d * NE);
        acc[0] += xv * w.x; acc[1] += xv * w.y; acc[2] += xv * w.z; acc[3] += xv * w.w;
    }
    __shared__ float sred[NE][8];
    int lane = threadIdx.x & 31, wid = threadIdx.x >> 5;
    #pragma unroll
    for (int e = 0; e < NE; e++) {
        float s = acc[e];
        #pragma unroll
        for (int off = 16; off > 0; off >>= 1) s += __shfl_down_sync(0xffffffffu, s, off);
        if (lane == 0) sred[e][wid] = s;
    }
    __syncthreads();
    if (threadIdx.x == 0) {
        float l[NE];
        #pragma unroll
        for (int e = 0; e < NE; e++) {
            float s = 0.f;
            #pragma unroll
            for (int w = 0; w < 8; w++) s += sred[e][w];
            l[e] = s;
        }
        float mx = fmaxf(fmaxf(l[0], l[1]), fmaxf(l[2], l[3]));
        float ex[NE], ssum = 0.f;
        #pragma unroll
        for (int e = 0; e < NE; e++) { ex[e] = expf(l[e] - mx); ssum += ex[e]; }
        float p[NE];
        #pragma unroll
        for (int e = 0; e < NE; e++) p[e] = ex[e] / ssum;
        int i1 = 0;
        #pragma unroll
        for (int e = 1; e < NE; e++) if (p[e] > p[i1]) i1 = e;
        int i2 = -1;
        #pragma unroll
        for (int e = 0; e < NE; e++)
            if (e != i1 && (i2 < 0 || p[e] > p[i2])) i2 = e;
        #pragma unroll
        for (int e = 0; e < NE; e++) {
            bool sel = (e == i1 || e == i2);
            g_gatew[e * NT + t] = sel ? p[e] : 0.f;
            if (sel) {
                int pos = atomicAdd(&g_counts[e], 1);
                g_lists[e * NT + pos] = t;
            }
        }
    }
}

// ---------------- weight transpose + fp16 pack ------------------------------
// src [E][K][N] fp32 -> dst [E][N][K] fp16.  One 32x32 tile per block.
// grid.x = 3 matrices * NE * (K/32)*(N/32);   block (32, 8)
__global__ __launch_bounds__(256) void wpack_kernel(const float* __restrict__ Wg,
                                                    const float* __restrict__ Wu,
                                                    const float* __restrict__ Wd) {
    __shared__ float s[32][33];
    const int TPM = NE * 16384;            // tiles per matrix ((K/32)*(N/32) = 16384 both shapes)
    int bid = blockIdx.x;
    const int m = bid / TPM;               // 0=Wg 1=Wu 2=Wd
    int r = bid % TPM;
    const int e = r / 16384;
    const int t = r % 16384;
    int K, N;
    const float* src;
    __half* dst;
    if (m == 0)      { K = ND; N = NF; src = Wg; dst = g_WgT; }
    else if (m == 1) { K = ND; N = NF; src = Wu; dst = g_WuT; }
    else             { K = NF; N = ND; src = Wd; dst = g_WdT; }
    const int ntiles = N / 32;
    const int tn = t % ntiles, tk = t / ntiles;
    const int k0 = tk * 32, n0 = tn * 32;
    src += (size_t)e * K * N;
    dst += (size_t)e * K * N;

    const int x = threadIdx.x, y = threadIdx.y;
    #pragma unroll
    for (int j = 0; j < 4; j++)
        s[y + 8*j][x] = src[(size_t)(k0 + y + 8*j) * N + n0 + x];
    __syncthreads();
    const int tid = y * 32 + x;
    #pragma unroll
    for (int jj = 0; jj < 2; jj++) {
        const int w  = tid + jj * 256;
        const int rr = w >> 4;          // n-row within tile
        const int c2 = w & 15;          // k-pair index
        uint32_t v = packh2(s[2*c2][rr], s[2*c2 + 1][rr]);
        *(uint32_t*)(dst + (size_t)(n0 + rr) * K + k0 + 2*c2) = v;
    }
}

// ---------------------------------------------------------------------------
// GATE+UP fused GEMM (fp16 m16n8k16, all-ldmatrix, cp.async 4-stage, BK=32,
// 256 thr, 2 CTA/SM). Block tile M=128, N=64 per matrix. Warp grid 2(M)x4(N):
// warptile 64x32. wn<2 -> G warp, wn>=2 -> U warp.
// A: [128 m][32 k] fp16, row stride 80 B (ldmatrix conflict-free)
// Bg/Bu: [64 n][32 k] fp16, row stride 80 B (ldmatrix conflict-free)
// ---------------------------------------------------------------------------
#define GU_AB 10240                      // 128*80
#define GU_BB 5120                       // 64*80 per matrix
#define GU_STAGE (GU_AB + 2*GU_BB)       // 20480 B
#define GU_SMEM (4 * GU_STAGE)           // 81920 B  (Us 128*68*4=34816 aliases)

__global__ __launch_bounds__(256, 2) void gateup_tc() {
    const int e  = blockIdx.z;
    const int Me = g_counts[e];
    const int m0 = blockIdx.x * 128;
    if (m0 >= Me) return;
    const int n0 = blockIdx.y * 64;

    extern __shared__ char smem[];
    const uint32_t sb0 = smem_u32(smem);

    const int tid  = threadIdx.x;
    const int warp = tid >> 5;
    const int lane = tid & 31;
    const int g4   = lane >> 2;
    const int t4   = lane & 3;
    const int wm   = warp >> 2;        // 0..1
    const int wn   = warp & 3;         // 0..3
    const int mat  = wn >> 1;          // 0=G, 1=U
    const int hn   = wn & 1;           // 32-col half

    // A staging: row = tid>>1, k-half = (tid&1)*16 halves; 2x16B
    const int ar  = tid >> 1;
    const int ahh = (tid & 1) * 16;
    int mrow = m0 + ar; if (mrow >= Me) mrow = Me - 1;
    const __half* asrc = g_Xh + (size_t)g_lists[e * NT + mrow] * ND + ahh;
    const uint32_t adst = sb0 + ar * 80 + ahh * 2;
    // B staging: 1 chunk/thread/matrix: row = tid>>2 (0..63), ch = tid&3
    const int brow = tid >> 2;
    const int bch  = tid & 3;
    const __half* bgsrc = g_WgT + ((size_t)e * NF + n0 + brow) * ND + bch * 8;
    const __half* busrc = g_WuT + ((size_t)e * NF + n0 + brow) * ND + bch * 8;
    const uint32_t bgdst = sb0 + GU_AB + brow * 80 + bch * 16;
    const uint32_t budst = bgdst + GU_BB;

    float acc[4][4][4];
    #pragma unroll
    for (int i = 0; i < 4; i++)
        #pragma unroll
        for (int j = 0; j < 4; j++)
            #pragma unroll
            for (int k = 0; k < 4; k++) acc[i][j][k] = 0.f;

    const int KT = ND / 32;    // 64
    auto issue = [&](int it) {
        const uint32_t so = (uint32_t)(it & 3) * GU_STAGE;
        const size_t   ka = (size_t)it * 32;
        cpa16(adst + so,      asrc + ka);
        cpa16(adst + so + 16, asrc + ka + 8);
        cpa16(bgdst + so, bgsrc + ka);
        cpa16(budst + so, busrc + ka);
    };

    issue(0); cpa_commit();
    issue(1); cpa_commit();
    issue(2); cpa_commit();

    // ldmatrix A base: rows (wm*64 + (lane&15)), k (lane>=16)*8 halves
    const uint32_t aldm = (wm * 64 + (lane & 15)) * 80 + ((lane >> 4) * 16);
    // ldmatrix B base: n-row = hn*32 + (lane>>4)*8 + (lane&7); k = ((lane>>3)&1)*8 halves
    const uint32_t bldm = GU_AB + mat * GU_BB +
        (hn * 32 + ((lane >> 4) << 3) + (lane & 7)) * 80 + (((lane >> 3) & 1) * 16);

    for (int it = 0; it < KT; ++it) {
        cpa_wait2();
        __syncthreads();
        if (it + 3 < KT) issue(it + 3);
        cpa_commit();

        const uint32_t st = sb0 + (uint32_t)(it & 3) * GU_STAGE;

        #pragma unroll
        for (int s = 0; s < 2; s++) {          // two k16 slices
            unsigned a[4][4];
            #pragma unroll
            for (int mi = 0; mi < 4; mi++)
                ldm4(a[mi], st + aldm + mi * 1280 + s * 32);
            #pragma unroll
            for (int p = 0; p < 2; p++) {      // n-row pair group: ni 2p, 2p+1
                unsigned bf[4];
                ldm4(bf, st + bldm + p * 1280 + s * 32);
                #pragma unroll
                for (int mi = 0; mi < 4; mi++) {
                    mma16(acc[mi][2*p],     a[mi], bf[0], bf[1]);
                    mma16(acc[mi][2*p + 1], a[mi], bf[2], bf[3]);
                }
            }
        }
    }

    // ---- epilogue: U warps stash; G warps write Hh = fp16(silu(G)*U) ----
    __syncthreads();
    float* Us = (float*)smem;                  // [128][68]
    if (mat == 1) {
        #pragma unroll
        for (int mi = 0; mi < 4; mi++)
            #pragma unroll
            for (int half = 0; half < 2; half++) {
                const int ml = wm * 64 + mi * 16 + g4 + half * 8;
                #pragma unroll
                for (int ni = 0; ni < 4; ni++) {
                    const int col = hn * 32 + ni * 8 + 2 * t4;
                    *(float2*)(Us + ml * 68 + col) =
                        make_float2(acc[mi][ni][half * 2], acc[mi][ni][half * 2 + 1]);
                }
            }
    }
    __syncthreads();
    if (mat == 0) {
        #pragma unroll
        for (int mi = 0; mi < 4; mi++)
            #pragma unroll
            for (int half = 0; half < 2; half++) {
                const int ml = wm * 64 + mi * 16 + g4 + half * 8;
                const int m  = m0 + ml;
                if (m >= Me) continue;
                __half* Hrow = g_Hh + ((size_t)e * NT + m) * NF + n0;
                #pragma unroll
                for (int ni = 0; ni < 4; ni++) {
                    const int col = hn * 32 + ni * 8 + 2 * t4;
                    float2 u = *(const float2*)(Us + ml * 68 + col);
                    float gv0 = acc[mi][ni][half * 2], gv1 = acc[mi][ni][half * 2 + 1];
                    float h0 = gv0 / (1.f + expf(-gv0)) * u.x;
                    float h1 = gv1 / (1.f + expf(-gv1)) * u.y;
                    *(uint32_t*)(Hrow + col) = packh2(h0, h1);
                }
            }
    }
}

// ---------------------------------------------------------------------------
// DOWN GEMM + combine (fp16 m16n8k16, all-ldmatrix, cp.async 4-stage, BK=32,
// 256 thr, 2 CTA/SM). Block tile 128x128. Warp grid 2(M)x4(N): warptile 64x32.
// A: [128 m][32 k] stride 80 B; B: [128 n][32 k] stride 80 B.
// ---------------------------------------------------------------------------
#define DN_AB 10240                      // 128*80
#define DN_BB 10240                      // 128*80
#define DN_STAGE (DN_AB + DN_BB)         // 20480 B
#define DN_SMEM (4 * DN_STAGE)           // 81920 B

__global__ __launch_bounds__(256, 2) void down_tc(float* __restrict__ OUT) {
    const int e  = blockIdx.z;
    const int Me = g_counts[e];
    const int m0 = blockIdx.x * 128;
    if (m0 >= Me) return;
    const int n0 = blockIdx.y * 128;

    extern __shared__ char smem[];
    const uint32_t sb0 = smem_u32(smem);

    const int tid  = threadIdx.x;
    const int warp = tid >> 5;
    const int lane = tid & 31;
    const int g4   = lane >> 2;
    const int t4   = lane & 3;
    const int wm   = warp >> 2;        // 0..1
    const int wn   = warp & 3;         // 0..3

    const int ar  = tid >> 1;
    const int ahh = (tid & 1) * 16;
    const __half* asrc = g_Hh + ((size_t)e * NT + m0 + ar) * NF + ahh;  // rows>=Me zeros
    const uint32_t adst = sb0 + ar * 80 + ahh * 2;

    const __half* bbase = g_WdT + ((size_t)e * ND + n0) * NF;

    float acc[4][4][4];
    #pragma unroll
    for (int i = 0; i < 4; i++)
        #pragma unroll
        for (int j = 0; j < 4; j++)
            #pragma unroll
            for (int k = 0; k < 4; k++) acc[i][j][k] = 0.f;

    const int KT = NF / 32;   // 256
    auto issue = [&](int it) {
        const uint32_t so = (uint32_t)(it & 3) * DN_STAGE;
        const size_t   ka = (size_t)it * 32;
        cpa16(adst + so,      asrc + ka);
        cpa16(adst + so + 16, asrc + ka + 8);
        #pragma unroll
        for (int j = 0; j < 2; j++) {
            const int c = j * 256 + tid;
            const int row = c >> 2, ch = c & 3;
            cpa16(sb0 + so + DN_AB + row * 80 + ch * 16,
                  bbase + (size_t)row * NF + ka + ch * 8);
        }
    };

    issue(0); cpa_commit();
    issue(1); cpa_commit();
    issue(2); cpa_commit();

    const uint32_t aldm = (wm * 64 + (lane & 15)) * 80 + ((lane >> 4) * 16);
    const uint32_t bldm = DN_AB +
        (wn * 32 + ((lane >> 4) << 3) + (lane & 7)) * 80 + (((lane >> 3) & 1) * 16);

    for (int it = 0; it < KT; ++it) {
        cpa_wait2();
        __syncthreads();
        if (it + 3 < KT) issue(it + 3);
        cpa_commit();

        const uint32_t st = sb0 + (uint32_t)(it & 3) * DN_STAGE;

        #pragma unroll
        for (int s = 0; s < 2; s++) {
            unsigned a[4][4];
            #pragma unroll
            for (int mi = 0; mi < 4; mi++)
                ldm4(a[mi], st + aldm + mi * 1280 + s * 32);
            #pragma unroll
            for (int p = 0; p < 2; p++) {
                unsigned bf[4];
                ldm4(bf, st + bldm + p * 1280 + s * 32);
                #pragma unroll
                for (int mi = 0; mi < 4; mi++) {
                    mma16(acc[mi][2*p],     a[mi], bf[0], bf[1]);
                    mma16(acc[mi][2*p + 1], a[mi], bf[2], bf[3]);
                }
            }
        }
    }

    #pragma unroll
    for (int mi = 0; mi < 4; mi++) {
        #pragma unroll
        for (int half = 0; half < 2; half++) {
            const int m = m0 + wm * 64 + mi * 16 + g4 + half * 8;
            if (m >= Me) continue;
            const int tok = g_lists[e * NT + m];
            const float w = g_gatew[e * NT + tok];
            float* dst = OUT + (size_t)tok * ND + n0 + wn * 32;
            #pragma unroll
            for (int ni = 0; ni < 4; ni++) {
                atomicAdd(dst + ni * 8 + 2 * t4,     w * acc[mi][ni][half * 2]);
                atomicAdd(dst + ni * 8 + 2 * t4 + 1, w * acc[mi][ni][half * 2 + 1]);
            }
        }
    }
}

// ---------------------------------------------------------------------------
extern "C" void kernel_launch(void* const* d_in, const int* in_sizes, int n_in,
                              void* d_out, int out_size) {
    const float* x  = (const float*)d_in[0];
    const float* Wr = (const float*)d_in[1];
    const float* Wg = (const float*)d_in[2];
    const float* Wu = (const float*)d_in[3];
    const float* Wd = (const float*)d_in[4];
    float* out = (float*)d_out;

    cudaFuncSetAttribute(gateup_tc, cudaFuncAttributeMaxDynamicSharedMemorySize, GU_SMEM);
    cudaFuncSetAttribute(down_tc,   cudaFuncAttributeMaxDynamicSharedMemorySize, DN_SMEM);

    prep_kernel<<<2048, 256>>>(x, out);                               // 0
    router_kernel<<<NT, 256>>>(x, Wr);                                // 1 (router+compact)
    wpack_kernel<<<3 * NE * 16384, dim3(32, 8)>>>(Wg, Wu, Wd);        // 2
    gateup_tc<<<dim3(NT/128, NF/64, NE), 256, GU_SMEM>>>();           // 3 (profiled slot)
    down_tc  <<<dim3(NT/128, ND/128, NE), 256, DN_SMEM>>>(out);       // 4
}

// round 15
// speedup vs baseline: 2.2803x; 1.1126x over previous
#include <cuda_runtime.h>
#include <cuda_fp16.h>
#include <math.h>
#include <stdint.h>

#define NB 2
#define NS 1024
#define NT (NB*NS)      // 2048 tokens
#define ND 2048
#define NF 8192
#define NE 4

// ---------------- persistent scratch (device globals) ----------------------
__device__ float    g_gatew[NE*NT];
__device__ int      g_counts[NE];
__device__ int      g_lists[NE*NT];
__device__ __half   g_Xh[(size_t)NT*ND];          // x, fp16 (k-contiguous rows)
__device__ __half   g_Hh[(size_t)NE*NT*NF];       // H = silu(G)*U fp16; rows >= Me stay 0
__device__ __half   g_WgT[(size_t)NE*NF*ND];      // Wg^T fp16 [E][N=F][K=D]
__device__ __half   g_WuT[(size_t)NE*NF*ND];      // Wu^T fp16 [E][N=F][K=D]
__device__ __half   g_WdT[(size_t)NE*ND*NF];      // Wd^T fp16 [E][N=D][K=F]

// ---------------- helpers ---------------------------------------------------
__device__ __forceinline__ uint32_t smem_u32(const void* p) {
    uint32_t a;
    asm("{ .reg .u64 t; cvta.to.shared.u64 t, %1; cvt.u32.u64 %0, t; }" : "=r"(a) : "l"(p));
    return a;
}
__device__ __forceinline__ uint32_t packh2(float lo, float hi) {
    __half2 h = __float22half2_rn(make_float2(lo, hi));   // lo -> low half (lower k)
    return *reinterpret_cast<uint32_t*>(&h);
}
__device__ __forceinline__ void cpa16(uint32_t dst, const void* src) {
    asm volatile("cp.async.cg.shared.global [%0], [%1], 16;" :: "r"(dst), "l"(src));
}
__device__ __forceinline__ void cpa_commit() { asm volatile("cp.async.commit_group;"); }
__device__ __forceinline__ void cpa_wait1()  { asm volatile("cp.async.wait_group 1;"); }

__device__ __forceinline__ void mma16(float c[4], const unsigned a[4],
                                      unsigned b0, unsigned b1) {
    asm volatile(
        "mma.sync.aligned.m16n8k16.row.col.f32.f16.f16.f32 "
        "{%0,%1,%2,%3}, {%4,%5,%6,%7}, {%8,%9}, {%0,%1,%2,%3};"
        : "+f"(c[0]), "+f"(c[1]), "+f"(c[2]), "+f"(c[3])
        : "r"(a[0]), "r"(a[1]), "r"(a[2]), "r"(a[3]), "r"(b0), "r"(b1));
}
__device__ __forceinline__ void ldm4(unsigned r[4], uint32_t addr) {
    asm volatile("ldmatrix.sync.aligned.m8n8.x4.shared.b16 {%0,%1,%2,%3}, [%4];"
        : "=r"(r[0]), "=r"(r[1]), "=r"(r[2]), "=r"(r[3]) : "r"(addr));
}

// ---------------- prep: zero out + counts, x -> fp16 ------------------------
__global__ void prep_kernel(const float* __restrict__ x, float* __restrict__ out) {
    const size_t n4 = (size_t)NT * ND / 4;
    const float4 z = make_float4(0.f, 0.f, 0.f, 0.f);
    for (size_t i = blockIdx.x * (size_t)blockDim.x + threadIdx.x; i < n4;
         i += (size_t)gridDim.x * blockDim.x) {
        ((float4*)out)[i] = z;
        float4 v = ((const float4*)x)[i];
        uint2 o;
        o.x = packh2(v.x, v.y);
        o.y = packh2(v.z, v.w);
        ((uint2*)g_Xh)[i] = o;
    }
    if (blockIdx.x == 0 && threadIdx.x < NE) g_counts[threadIdx.x] = 0;
}

// ---------------- router (+ fused compaction) -------------------------------
__global__ void router_kernel(const float* __restrict__ x, const float* __restrict__ Wr) {
    int t = blockIdx.x;
    const float* xr = x + (size_t)t * ND;
    float acc[NE] = {0.f, 0.f, 0.f, 0.f};
    for (int d = threadIdx.x; d < ND; d += blockDim.x) {
        float xv = xr[d];
        float4 w = *(const float4*)(Wr + d * NE);
        acc[0] += xv * w.x; acc[1] += xv * w.y; acc[2] += xv * w.z; acc[3] += xv * w.w;
    }
    __shared__ float sred[NE][8];
    int lane = threadIdx.x & 31, wid = threadIdx.x >> 5;
    #pragma unroll
    for (int e = 0; e < NE; e++) {
        float s = acc[e];
        #pragma unroll
        for (int off = 16; off > 0; off >>= 1) s += __shfl_down_sync(0xffffffffu, s, off);
        if (lane == 0) sred[e][wid] = s;
    }
    __syncthreads();
    if (threadIdx.x == 0) {
        float l[NE];
        #pragma unroll
        for (int e = 0; e < NE; e++) {
            float s = 0.f;
            #pragma unroll
            for (int w = 0; w < 8; w++) s += sred[e][w];
            l[e] = s;
        }
        float mx = fmaxf(fmaxf(l[0], l[1]), fmaxf(l[2], l[3]));
        float ex[NE], ssum = 0.f;
        #pragma unroll
        for (int e = 0; e < NE; e++) { ex[e] = expf(l[e] - mx); ssum += ex[e]; }
        float p[NE];
        #pragma unroll
        for (int e = 0; e < NE; e++) p[e] = ex[e] / ssum;
        int i1 = 0;
        #pragma unroll
        for (int e = 1; e < NE; e++) if (p[e] > p[i1]) i1 = e;
        int i2 = -1;
        #pragma unroll
        for (int e = 0; e < NE; e++)
            if (e != i1 && (i2 < 0 || p[e] > p[i2])) i2 = e;
        #pragma unroll
        for (int e = 0; e < NE; e++) {
            bool sel = (e == i1 || e == i2);
            g_gatew[e * NT + t] = sel ? p[e] : 0.f;
            if (sel) {
                int pos = atomicAdd(&g_counts[e], 1);
                g_lists[e * NT + pos] = t;
            }
        }
    }
}

// ---------------- weight transpose + fp16 pack ------------------------------
// src [E][K][N] fp32 -> dst [E][N][K] fp16.  One 32x32 tile per block.
__global__ __launch_bounds__(256) void wpack_kernel(const float* __restrict__ Wg,
                                                    const float* __restrict__ Wu,
                                                    const float* __restrict__ Wd) {
    __shared__ float s[32][33];
    const int TPM = NE * 16384;
    int bid = blockIdx.x;
    const int m = bid / TPM;               // 0=Wg 1=Wu 2=Wd
    int r = bid % TPM;
    const int e = r / 16384;
    const int t = r % 16384;
    int K, N;
    const float* src;
    __half* dst;
    if (m == 0)      { K = ND; N = NF; src = Wg; dst = g_WgT; }
    else if (m == 1) { K = ND; N = NF; src = Wu; dst = g_WuT; }
    else             { K = NF; N = ND; src = Wd; dst = g_WdT; }
    const int ntiles = N / 32;
    const int tn = t % ntiles, tk = t / ntiles;
    const int k0 = tk * 32, n0 = tn * 32;
    src += (size_t)e * K * N;
    dst += (size_t)e * K * N;

    const int x = threadIdx.x, y = threadIdx.y;
    #pragma unroll
    for (int j = 0; j < 4; j++)
        s[y + 8*j][x] = src[(size_t)(k0 + y + 8*j) * N + n0 + x];
    __syncthreads();
    const int tid = y * 32 + x;
    #pragma unroll
    for (int jj = 0; jj < 2; jj++) {
        const int w  = tid + jj * 256;
        const int rr = w >> 4;
        const int c2 = w & 15;
        uint32_t v = packh2(s[2*c2][rr], s[2*c2 + 1][rr]);
        *(uint32_t*)(dst + (size_t)(n0 + rr) * K + k0 + 2*c2) = v;
    }
}

// ---------------------------------------------------------------------------
// GATE+UP fused GEMM (fp16 m16n8k16, all-ldmatrix, cp.async 3-stage, BK=64,
// 256 thr, 2 CTA/SM). Block tile M=128, N=64 per matrix. Warp grid 2(M)x4(N):
// warptile 64x32. wn<2 -> G warp, wn>=2 -> U warp.
// Row stride 144 B (36 words == 4 mod 32 -> conflict-free ldmatrix).
// A: [128 m][64 k]; Bg/Bu: [64 n][64 k].
// ---------------------------------------------------------------------------
#define RS 144                           // row stride bytes (64 halves + 8 pad)
#define GU_AB (128*RS)                   // 18432
#define GU_BB (64*RS)                    // 9216 per matrix
#define GU_STAGE (GU_AB + 2*GU_BB)       // 36864 B
#define GU_SMEM (3 * GU_STAGE)           // 110592 B

__global__ __launch_bounds__(256, 2) void gateup_tc() {
    const int e  = blockIdx.z;
    const int Me = g_counts[e];
    const int m0 = blockIdx.x * 128;
    if (m0 >= Me) return;
    const int n0 = blockIdx.y * 64;

    extern __shared__ char smem[];
    const uint32_t sb0 = smem_u32(smem);

    const int tid  = threadIdx.x;
    const int warp = tid >> 5;
    const int lane = tid & 31;
    const int g4   = lane >> 2;
    const int t4   = lane & 3;
    const int wm   = warp >> 2;        // 0..1
    const int wn   = warp & 3;         // 0..3
    const int mat  = wn >> 1;          // 0=G, 1=U
    const int hn   = wn & 1;           // 32-col half

    // A staging: 1024 chunks (8 per row): c = j*256+tid: row = c>>3, ch = c&7
    const int arow = tid >> 3, ach = tid & 7;
    // rows handled by this thread: arow + j*32 (j=0..3)
    const __half* asrc[4];
    #pragma unroll
    for (int j = 0; j < 4; j++) {
        int mrow = m0 + arow + j * 32; if (mrow >= Me) mrow = Me - 1;
        asrc[j] = g_Xh + (size_t)g_lists[e * NT + mrow] * ND + ach * 8;
    }
    const uint32_t adst0 = sb0 + arow * RS + ach * 16;
    // B staging: 512 chunks per matrix: c = j*256+tid: row = c>>3, ch = c&7
    const __half* bgsrc = g_WgT + ((size_t)e * NF + n0 + arow) * ND + ach * 8;
    const __half* busrc = g_WuT + ((size_t)e * NF + n0 + arow) * ND + ach * 8;
    const uint32_t bgdst0 = sb0 + GU_AB + arow * RS + ach * 16;

    float acc[4][4][4];
    #pragma unroll
    for (int i = 0; i < 4; i++)
        #pragma unroll
        for (int j = 0; j < 4; j++)
            #pragma unroll
            for (int k = 0; k < 4; k++) acc[i][j][k] = 0.f;

    const int KT = ND / 64;    // 32
    auto issue = [&](int it) {
        const uint32_t so = (uint32_t)(it % 3) * GU_STAGE;
        const size_t   ka = (size_t)it * 64;
        #pragma unroll
        for (int j = 0; j < 4; j++)
            cpa16(adst0 + so + j * 32 * RS, asrc[j] + ka);
        #pragma unroll
        for (int j = 0; j < 2; j++) {
            cpa16(bgdst0 + so + j * 32 * RS,         bgsrc + (size_t)j * 32 * ND + ka);
            cpa16(bgdst0 + so + GU_BB + j * 32 * RS, busrc + (size_t)j * 32 * ND + ka);
        }
    };

    issue(0); cpa_commit();
    issue(1); cpa_commit();

    // ldmatrix bases
    const uint32_t aldm = (wm * 64 + (lane & 15)) * RS + ((lane >> 4) * 16);
    const uint32_t bldm = GU_AB + mat * GU_BB +
        (hn * 32 + ((lane >> 4) << 3) + (lane & 7)) * RS + (((lane >> 3) & 1) * 16);

    for (int it = 0; it < KT; ++it) {
        cpa_wait1();               // groups {it, it+1} pending -> group it complete
        __syncthreads();
        if (it + 2 < KT) issue(it + 2);
        cpa_commit();

        const uint32_t st = sb0 + (uint32_t)(it % 3) * GU_STAGE;

        #pragma unroll
        for (int s = 0; s < 4; s++) {          // four k16 slices
            unsigned a[4][4];
            #pragma unroll
            for (int mi = 0; mi < 4; mi++)
                ldm4(a[mi], st + aldm + mi * 16 * RS + s * 32);
            #pragma unroll
            for (int p = 0; p < 2; p++) {
                unsigned bf[4];
                ldm4(bf, st + bldm + p * 16 * RS + s * 32);
                #pragma unroll
                for (int mi = 0; mi < 4; mi++) {
                    mma16(acc[mi][2*p],     a[mi], bf[0], bf[1]);
                    mma16(acc[mi][2*p + 1], a[mi], bf[2], bf[3]);
                }
            }
        }
    }

    // ---- epilogue: U warps stash; G warps write Hh = fp16(silu(G)*U) ----
    __syncthreads();
    float* Us = (float*)smem;                  // [128][68]
    if (mat == 1) {
        #pragma unroll
        for (int mi = 0; mi < 4; mi++)
            #pragma unroll
            for (int half = 0; half < 2; half++) {
                const int ml = wm * 64 + mi * 16 + g4 + half * 8;
                #pragma unroll
                for (int ni = 0; ni < 4; ni++) {
                    const int col = hn * 32 + ni * 8 + 2 * t4;
                    *(float2*)(Us + ml * 68 + col) =
                        make_float2(acc[mi][ni][half * 2], acc[mi][ni][half * 2 + 1]);
                }
            }
    }
    __syncthreads();
    if (mat == 0) {
        #pragma unroll
        for (int mi = 0; mi < 4; mi++)
            #pragma unroll
            for (int half = 0; half < 2; half++) {
                const int ml = wm * 64 + mi * 16 + g4 + half * 8;
                const int m  = m0 + ml;
                if (m >= Me) continue;
                __half* Hrow = g_Hh + ((size_t)e * NT + m) * NF + n0;
                #pragma unroll
                for (int ni = 0; ni < 4; ni++) {
                    const int col = hn * 32 + ni * 8 + 2 * t4;
                    float2 u = *(const float2*)(Us + ml * 68 + col);
                    float gv0 = acc[mi][ni][half * 2], gv1 = acc[mi][ni][half * 2 + 1];
                    float h0 = gv0 / (1.f + expf(-gv0)) * u.x;
                    float h1 = gv1 / (1.f + expf(-gv1)) * u.y;
                    *(uint32_t*)(Hrow + col) = packh2(h0, h1);
                }
            }
    }
}

// ---------------------------------------------------------------------------
// DOWN GEMM + combine (fp16 m16n8k16, all-ldmatrix, cp.async 3-stage, BK=64,
// 256 thr, 2 CTA/SM). Block tile 128x128. Warp grid 2(M)x4(N): warptile 64x32.
// A: [128 m][64 k]; B: [128 n][64 k]; row stride 144 B.
// ---------------------------------------------------------------------------
#define DN_AB (128*RS)                   // 18432
#define DN_BB (128*RS)                   // 18432
#define DN_STAGE (DN_AB + DN_BB)         // 36864 B
#define DN_SMEM (3 * DN_STAGE)           // 110592 B

__global__ __launch_bounds__(256, 2) void down_tc(float* __restrict__ OUT) {
    const int e  = blockIdx.z;
    const int Me = g_counts[e];
    const int m0 = blockIdx.x * 128;
    if (m0 >= Me) return;
    const int n0 = blockIdx.y * 128;

    extern __shared__ char smem[];
    const uint32_t sb0 = smem_u32(smem);

    const int tid  = threadIdx.x;
    const int warp = tid >> 5;
    const int lane = tid & 31;
    const int g4   = lane >> 2;
    const int t4   = lane & 3;
    const int wm   = warp >> 2;        // 0..1
    const int wn   = warp & 3;         // 0..3

    const int arow = tid >> 3, ach = tid & 7;
    const __half* asrc = g_Hh + ((size_t)e * NT + m0 + arow) * NF + ach * 8;  // rows>=Me zeros
    const uint32_t adst0 = sb0 + arow * RS + ach * 16;
    const __half* bsrc = g_WdT + ((size_t)e * ND + n0 + arow) * NF + ach * 8;
    const uint32_t bdst0 = sb0 + DN_AB + arow * RS + ach * 16;

    float acc[4][4][4];
    #pragma unroll
    for (int i = 0; i < 4; i++)
        #pragma unroll
        for (int j = 0; j < 4; j++)
            #pragma unroll
            for (int k = 0; k < 4; k++) acc[i][j][k] = 0.f;

    const int KT = NF / 64;   // 128
    auto issue = [&](int it) {
        const uint32_t so = (uint32_t)(it % 3) * DN_STAGE;
        const size_t   ka = (size_t)it * 64;
        #pragma unroll
        for (int j = 0; j < 4; j++) {
            cpa16(adst0 + so + j * 32 * RS, asrc + (size_t)j * 32 * NF + ka);
            cpa16(bdst0 + so + j * 32 * RS, bsrc + (size_t)j * 32 * NF + ka);
        }
    };

    issue(0); cpa_commit();
    issue(1); cpa_commit();

    const uint32_t aldm = (wm * 64 + (lane & 15)) * RS + ((lane >> 4) * 16);
    const uint32_t bldm = DN_AB +
        (wn * 32 + ((lane >> 4) << 3) + (lane & 7)) * RS + (((lane >> 3) & 1) * 16);

    for (int it = 0; it < KT; ++it) {
        cpa_wait1();
        __syncthreads();
        if (it + 2 < KT) issue(it + 2);
        cpa_commit();

        const uint32_t st = sb0 + (uint32_t)(it % 3) * DN_STAGE;

        #pragma unroll
        for (int s = 0; s < 4; s++) {
            unsigned a[4][4];
            #pragma unroll
            for (int mi = 0; mi < 4; mi++)
                ldm4(a[mi], st + aldm + mi * 16 * RS + s * 32);
            #pragma unroll
            for (int p = 0; p < 2; p++) {
                unsigned bf[4];
                ldm4(bf, st + bldm + p * 16 * RS + s * 32);
                #pragma unroll
                for (int mi = 0; mi < 4; mi++) {
                    mma16(acc[mi][2*p],     a[mi], bf[0], bf[1]);
                    mma16(acc[mi][2*p + 1], a[mi], bf[2], bf[3]);
                }
            }
        }
    }

    #pragma unroll
    for (int mi = 0; mi < 4; mi++) {
        #pragma unroll
        for (int half = 0; half < 2; half++) {
            const int m = m0 + wm * 64 + mi * 16 + g4 + half * 8;
            if (m >= Me) continue;
            const int tok = g_lists[e * NT + m];
            const float w = g_gatew[e * NT + tok];
            float* dst = OUT + (size_t)tok * ND + n0 + wn * 32;
            #pragma unroll
            for (int ni = 0; ni < 4; ni++) {
                atomicAdd(dst + ni * 8 + 2 * t4,     w * acc[mi][ni][half * 2]);
                atomicAdd(dst + ni * 8 + 2 * t4 + 1, w * acc[mi][ni][half * 2 + 1]);
            }
        }
    }
}

// ---------------------------------------------------------------------------
extern "C" void kernel_launch(void* const* d_in, const int* in_sizes, int n_in,
                              void* d_out, int out_size) {
    const float* x  = (const float*)d_in[0];
    const float* Wr = (const float*)d_in[1];
    const float* Wg = (const float*)d_in[2];
    const float* Wu = (const float*)d_in[3];
    const float* Wd = (const float*)d_in[4];
    float* out = (float*)d_out;

    cudaFuncSetAttribute(gateup_tc, cudaFuncAttributeMaxDynamicSharedMemorySize, GU_SMEM);
    cudaFuncSetAttribute(down_tc,   cudaFuncAttributeMaxDynamicSharedMemorySize, DN_SMEM);

    prep_kernel<<<2048, 256>>>(x, out);                               // 0
    router_kernel<<<NT, 256>>>(x, Wr);                                // 1 (router+compact)
    wpack_kernel<<<3 * NE * 16384, dim3(32, 8)>>>(Wg, Wu, Wd);        // 2
    gateup_tc<<<dim3(NT/128, NF/64, NE), 256, GU_SMEM>>>();           // 3 (profiled slot)
    down_tc  <<<dim3(NT/128, ND/128, NE), 256, DN_SMEM>>>(out);       // 4
}